// round 2
// baseline (speedup 1.0000x reference)
#include <cuda_runtime.h>
#include <math.h>

// ---------------------------------------------------------------------------
// Problem constants
// ---------------------------------------------------------------------------
#define EPSV 2.2e-10f
#define VDIM 30000
#define BDIM 512
#define K0 128
#define K1 64
#define K2 32

#define OFF1 (VDIM * K0)            // 3,840,000
#define OFF2 (OFF1 + K0 * K1)       // 3,848,192

// split-K / chunk configs (all divide exactly)
#define NS0 60                      // splits for phi0^T @ ratio0 (30000/60 = 500)
#define VCH 500
#define NCH 120                     // row chunks for column reductions (30000/120 = 250)
#define RCH 250

// ---------------------------------------------------------------------------
// Device scratch (no allocations allowed)
// ---------------------------------------------------------------------------
__device__ float g_xT[VDIM * BDIM];          // x transposed (V,B)
__device__ float g_ratio0[VDIM * BDIM];      // (V,B)
__device__ float g_WSZS0[VDIM * K0];         // (V,K0)
__device__ float g_x1part[NS0 * K0 * BDIM];  // split-K partials
__device__ float g_X1[K0 * BDIM];            // layer-1 counts (K0,B)
__device__ float g_c0part[NCH * 3 * K0];
__device__ float g_c0[4 * K0];               // inv_n, beta, tmpsum, (step_sum-1)
__device__ float g_ppart[NCH * K0];
__device__ float g_pinv0[K0];
__device__ float g_ratio1[K0 * BDIM];
__device__ float g_l1wp[8 * K0 * K1];
__device__ float g_X2[K1 * BDIM];            // layer-2 counts (K1,B)
__device__ float g_ratio2[K1 * BDIM];
__device__ float g_l2wp[8 * K1 * K2];

// ---------------------------------------------------------------------------
// fp32 digamma (FP64 is slow on this part -> avoid DFMA entirely)
// recurrence to x>=6, then 5-term asymptotic series; rel err << 1e-3
// ---------------------------------------------------------------------------
__device__ __forceinline__ float digammaf_(float x) {
    float r = 0.f;
    while (x < 6.f) { r -= 1.f / x; x += 1.f; }
    float inv  = 1.f / x;
    float inv2 = inv * inv;
    float s = logf(x) - 0.5f * inv
        - inv2 * (0.083333333333f
        - inv2 * (0.008333333333f
        - inv2 * (0.003968253968f
        - inv2 * (0.004166666667f
        - inv2 * 0.007575757576f))));
    return r + s;
}

// ---------------------------------------------------------------------------
// 1) transpose x (B,V) -> g_xT (V,B)
// ---------------------------------------------------------------------------
__global__ void k_transpose(const float* __restrict__ x) {
    __shared__ float tile[32][33];
    int v0 = blockIdx.x * 32, b0 = blockIdx.y * 32;
    int tx = threadIdx.x, ty = threadIdx.y;   // (32, 8)
#pragma unroll
    for (int i = 0; i < 32; i += 8) {
        int v = v0 + tx, b = b0 + ty + i;
        tile[ty + i][tx] = (v < VDIM) ? x[(size_t)b * VDIM + v] : 0.f;
    }
    __syncthreads();
#pragma unroll
    for (int i = 0; i < 32; i += 8) {
        int v = v0 + ty + i, b = b0 + tx;
        if (v < VDIM) g_xT[(size_t)v * BDIM + b] = tile[tx][ty + i];
    }
}

// ---------------------------------------------------------------------------
// 2) ratio0 = xT / max(phi0 @ theta0, EPS)      tiles 128x128, K=128
// ---------------------------------------------------------------------------
__global__ void __launch_bounds__(256)
k_ratio0(const float* __restrict__ phi0, const float* __restrict__ theta0) {
    __shared__ float As[32][132];
    __shared__ float Bs[32][128];
    int tid = threadIdx.x;
    int v0 = blockIdx.x * 128, b0 = blockIdx.y * 128;
    int tx = tid & 15, ty = tid >> 4;
    int row = ty * 8, col = tx * 8;
    float acc[8][8] = {};
    for (int k0 = 0; k0 < K0; k0 += 32) {
#pragma unroll
        for (int p = 0; p < 4; p++) {
            int slot = tid + p * 256;
            int r = slot >> 3, c4 = (slot & 7) * 4;
            float4 a = make_float4(0.f, 0.f, 0.f, 0.f);
            if (v0 + r < VDIM)
                a = *(const float4*)&phi0[(size_t)(v0 + r) * K0 + k0 + c4];
            As[c4 + 0][r] = a.x; As[c4 + 1][r] = a.y;
            As[c4 + 2][r] = a.z; As[c4 + 3][r] = a.w;
        }
#pragma unroll
        for (int p = 0; p < 4; p++) {
            int slot = tid + p * 256;
            int c = slot >> 5, j4 = (slot & 31) * 4;
            *(float4*)&Bs[c][j4] =
                *(const float4*)&theta0[(size_t)(k0 + c) * BDIM + b0 + j4];
        }
        __syncthreads();
#pragma unroll
        for (int c = 0; c < 32; c++) {
            float ra[8], rb[8];
#pragma unroll
            for (int i = 0; i < 8; i++) ra[i] = As[c][row + i];
#pragma unroll
            for (int j = 0; j < 8; j++) rb[j] = Bs[c][col + j];
#pragma unroll
            for (int i = 0; i < 8; i++)
#pragma unroll
                for (int j = 0; j < 8; j++) acc[i][j] += ra[i] * rb[j];
        }
        __syncthreads();
    }
#pragma unroll
    for (int i = 0; i < 8; i++) {
        int v = v0 + row + i;
        if (v >= VDIM) break;
#pragma unroll
        for (int j = 0; j < 8; j += 4) {
            float4 xv = *(const float4*)&g_xT[(size_t)v * BDIM + b0 + col + j];
            float4 o;
            o.x = xv.x / fmaxf(acc[i][j + 0], EPSV);
            o.y = xv.y / fmaxf(acc[i][j + 1], EPSV);
            o.z = xv.z / fmaxf(acc[i][j + 2], EPSV);
            o.w = xv.w / fmaxf(acc[i][j + 3], EPSV);
            *(float4*)&g_ratio0[(size_t)v * BDIM + b0 + col + j] = o;
        }
    }
}

// ---------------------------------------------------------------------------
// 3) WSZS0 = phi0 * (ratio0 @ theta0^T)   tiles 128(v)x128(k), K=512 over b
// ---------------------------------------------------------------------------
__global__ void __launch_bounds__(256)
k_wszs0(const float* __restrict__ phi0, const float* __restrict__ theta0) {
    __shared__ float As[32][132];
    __shared__ float Bs[32][132];
    int tid = threadIdx.x;
    int v0 = blockIdx.x * 128;
    int tx = tid & 15, ty = tid >> 4;
    int row = ty * 8, col = tx * 8;
    float acc[8][8] = {};
    for (int b0 = 0; b0 < BDIM; b0 += 32) {
#pragma unroll
        for (int p = 0; p < 4; p++) {
            int slot = tid + p * 256;
            int r = slot >> 3, c4 = (slot & 7) * 4;
            float4 a = make_float4(0.f, 0.f, 0.f, 0.f);
            if (v0 + r < VDIM)
                a = *(const float4*)&g_ratio0[(size_t)(v0 + r) * BDIM + b0 + c4];
            As[c4 + 0][r] = a.x; As[c4 + 1][r] = a.y;
            As[c4 + 2][r] = a.z; As[c4 + 3][r] = a.w;
        }
#pragma unroll
        for (int p = 0; p < 4; p++) {
            int slot = tid + p * 256;
            int k = slot >> 3, c4 = (slot & 7) * 4;
            float4 t = *(const float4*)&theta0[(size_t)k * BDIM + b0 + c4];
            Bs[c4 + 0][k] = t.x; Bs[c4 + 1][k] = t.y;
            Bs[c4 + 2][k] = t.z; Bs[c4 + 3][k] = t.w;
        }
        __syncthreads();
#pragma unroll
        for (int c = 0; c < 32; c++) {
            float ra[8], rb[8];
#pragma unroll
            for (int i = 0; i < 8; i++) ra[i] = As[c][row + i];
#pragma unroll
            for (int j = 0; j < 8; j++) rb[j] = Bs[c][col + j];
#pragma unroll
            for (int i = 0; i < 8; i++)
#pragma unroll
                for (int j = 0; j < 8; j++) acc[i][j] += ra[i] * rb[j];
        }
        __syncthreads();
    }
#pragma unroll
    for (int i = 0; i < 8; i++) {
        int v = v0 + row + i;
        if (v >= VDIM) break;
#pragma unroll
        for (int j = 0; j < 8; j += 4) {
            float4 ph = *(const float4*)&phi0[(size_t)v * K0 + col + j];
            float4 o;
            o.x = ph.x * acc[i][j + 0];
            o.y = ph.y * acc[i][j + 1];
            o.z = ph.z * acc[i][j + 2];
            o.w = ph.w * acc[i][j + 3];
            *(float4*)&g_WSZS0[(size_t)v * K0 + col + j] = o;
        }
    }
}

// ---------------------------------------------------------------------------
// 4) split-K partials of phi0^T @ ratio0 -> (K0, B) per split (deterministic)
// ---------------------------------------------------------------------------
__global__ void __launch_bounds__(256)
k_x1part(const float* __restrict__ phi0) {
    __shared__ float As[32][128];   // [vv][k]
    __shared__ float Bs[32][128];   // [vv][b]
    int tid = threadIdx.x;
    int b0 = blockIdx.x * 128;
    int s  = blockIdx.y;
    int vbeg = s * VCH, vend = vbeg + VCH;
    int tx = tid & 15, ty = tid >> 4;
    int row = ty * 8, col = tx * 8;   // row over k, col over b
    float acc[8][8] = {};
    for (int v0 = vbeg; v0 < vend; v0 += 32) {
#pragma unroll
        for (int p = 0; p < 4; p++) {
            int slot = tid + p * 256;
            int vv = slot >> 5, j4 = (slot & 31) * 4;
            float4 a = make_float4(0.f, 0.f, 0.f, 0.f);
            if (v0 + vv < vend)
                a = *(const float4*)&phi0[(size_t)(v0 + vv) * K0 + j4];
            *(float4*)&As[vv][j4] = a;
        }
#pragma unroll
        for (int p = 0; p < 4; p++) {
            int slot = tid + p * 256;
            int vv = slot >> 5, j4 = (slot & 31) * 4;
            float4 bvl = make_float4(0.f, 0.f, 0.f, 0.f);
            if (v0 + vv < vend)
                bvl = *(const float4*)&g_ratio0[(size_t)(v0 + vv) * BDIM + b0 + j4];
            *(float4*)&Bs[vv][j4] = bvl;
        }
        __syncthreads();
#pragma unroll
        for (int c = 0; c < 32; c++) {
            float ra[8], rb[8];
#pragma unroll
            for (int i = 0; i < 8; i++) ra[i] = As[c][row + i];
#pragma unroll
            for (int j = 0; j < 8; j++) rb[j] = Bs[c][col + j];
#pragma unroll
            for (int i = 0; i < 8; i++)
#pragma unroll
                for (int j = 0; j < 8; j++) acc[i][j] += ra[i] * rb[j];
        }
        __syncthreads();
    }
    float* dst = &g_x1part[(size_t)s * K0 * BDIM];
#pragma unroll
    for (int i = 0; i < 8; i++)
#pragma unroll
        for (int j = 0; j < 8; j += 4)
            *(float4*)&dst[(size_t)(row + i) * BDIM + b0 + col + j] =
                make_float4(acc[i][j], acc[i][j + 1], acc[i][j + 2], acc[i][j + 3]);
}

// 5) reduce partials, multiply by theta0 -> X1
__global__ void k_x1red(const float* __restrict__ theta0) {
    int idx = blockIdx.x * 1024 + threadIdx.x;   // < 65536
    float s = 0.f;
#pragma unroll 4
    for (int p = 0; p < NS0; p++) s += g_x1part[(size_t)p * K0 * BDIM + idx];
    g_X1[idx] = theta0[idx] * s;
}

// ---------------------------------------------------------------------------
// 6/7) column stats for layer-0 TLASGR (deterministic two-stage)
// ---------------------------------------------------------------------------
__global__ void k_colA(const float* __restrict__ phi0,
                       const float* __restrict__ noise0) {
    int t = threadIdx.x;              // column
    int ch = blockIdx.x;
    float sw = 0.f, sp = 0.f, sn = 0.f;
    int vbeg = ch * RCH;
#pragma unroll 4
    for (int r = 0; r < RCH; r++) {
        size_t idx = (size_t)(vbeg + r) * K0 + t;
        sw += g_WSZS0[idx];
        float ph = phi0[idx];
        sp += ph;
        sn += sqrtf(ph) * noise0[idx];
    }
    g_c0part[ch * 384 + t]        = sw;
    g_c0part[ch * 384 + 128 + t]  = sp;
    g_c0part[ch * 384 + 256 + t]  = sn;
}

__global__ void k_colB() {
    int t = threadIdx.x;
    float sw = 0.f, sp = 0.f, sn = 0.f;
    for (int ch = 0; ch < NCH; ch++) {
        sw += g_c0part[ch * 384 + t];
        sp += g_c0part[ch * 384 + 128 + t];
        sn += g_c0part[ch * 384 + 256 + t];
    }
    float NDot   = 100.f * sw;
    float tmpsum = NDot + 0.1f * (float)VDIM;
    float inv_n  = 1.f / fmaxf(NDot, EPSV);
    float beta   = sqrtf(2.f * inv_n);
    float ssum   = sp + inv_n * (tmpsum - tmpsum * sp) + beta * sn;
    g_c0[t]           = inv_n;
    g_c0[128 + t]     = beta;
    g_c0[256 + t]     = tmpsum;
    g_c0[384 + t]     = ssum - 1.f;
}

// 8) p = max(EPS, step - (ssum-1)*phi); write + per-chunk psum
__global__ void k_p0(const float* __restrict__ phi0,
                     const float* __restrict__ noise0,
                     float* __restrict__ out) {
    int t = threadIdx.x;
    int ch = blockIdx.x;
    float inv_n = g_c0[t], beta = g_c0[128 + t];
    float tmpsum = g_c0[256 + t], c3 = g_c0[384 + t];
    float psum = 0.f;
    int vbeg = ch * RCH;
#pragma unroll 4
    for (int r = 0; r < RCH; r++) {
        size_t idx = (size_t)(vbeg + r) * K0 + t;
        float ph  = phi0[idx];
        float tmp = 100.f * g_WSZS0[idx] + 0.1f;
        float step = ph + inv_n * (tmp - tmpsum * ph)
                   + beta * sqrtf(ph) * noise0[idx];
        float p = fmaxf(EPSV, step - c3 * ph);
        out[idx] = p;
        psum += p;
    }
    g_ppart[ch * K0 + t] = psum;
}

__global__ void k_psumfin() {
    int t = threadIdx.x;
    float s = 0.f;
    for (int ch = 0; ch < NCH; ch++) s += g_ppart[ch * K0 + t];
    g_pinv0[t] = 1.f / fmaxf(EPSV, s);
}

__global__ void k_norm0(float* __restrict__ out) {
    int idx = blockIdx.x * 1024 + threadIdx.x;   // 3750*1024 = 3,840,000
    out[idx] *= g_pinv0[idx & 127];
}

// ---------------------------------------------------------------------------
// Layer 1: ratio1 = digamma(denom+X1)-digamma(denom), denom = phi1@theta1
//          tiles 128x128, K=64
// ---------------------------------------------------------------------------
__global__ void __launch_bounds__(256)
k_l1ratio(const float* __restrict__ phi1, const float* __restrict__ theta1) {
    __shared__ float As[32][132];
    __shared__ float Bs[32][128];
    int tid = threadIdx.x;
    int b0 = blockIdx.x * 128;
    int tx = tid & 15, ty = tid >> 4;
    int row = ty * 8, col = tx * 8;
    float acc[8][8] = {};
    for (int k0 = 0; k0 < K1; k0 += 32) {
#pragma unroll
        for (int p = 0; p < 4; p++) {
            int slot = tid + p * 256;
            int r = slot >> 3, c4 = (slot & 7) * 4;
            float4 a = *(const float4*)&phi1[(size_t)r * K1 + k0 + c4];
            As[c4 + 0][r] = a.x; As[c4 + 1][r] = a.y;
            As[c4 + 2][r] = a.z; As[c4 + 3][r] = a.w;
        }
#pragma unroll
        for (int p = 0; p < 4; p++) {
            int slot = tid + p * 256;
            int c = slot >> 5, j4 = (slot & 31) * 4;
            *(float4*)&Bs[c][j4] =
                *(const float4*)&theta1[(size_t)(k0 + c) * BDIM + b0 + j4];
        }
        __syncthreads();
#pragma unroll
        for (int c = 0; c < 32; c++) {
            float ra[8], rb[8];
#pragma unroll
            for (int i = 0; i < 8; i++) ra[i] = As[c][row + i];
#pragma unroll
            for (int j = 0; j < 8; j++) rb[j] = Bs[c][col + j];
#pragma unroll
            for (int i = 0; i < 8; i++)
#pragma unroll
                for (int j = 0; j < 8; j++) acc[i][j] += ra[i] * rb[j];
        }
        __syncthreads();
    }
#pragma unroll
    for (int i = 0; i < 8; i++) {
        int v = row + i;
#pragma unroll
        for (int j = 0; j < 8; j++) {
            float d  = fmaxf(acc[i][j], EPSV);
            float xv = g_X1[(size_t)v * BDIM + b0 + col + j];
            g_ratio1[(size_t)v * BDIM + b0 + col + j] =
                digammaf_(d + xv) - digammaf_(d);
        }
    }
}

// Layer 1 WSZS partials: (128 x 64) = ratio1 @ theta1^T, split-K over b (8x64)
__global__ void k_l1wszs(const float* __restrict__ theta1) {
    __shared__ float As[32][132];
    __shared__ float Bs[32][68];
    int tid = threadIdx.x;
    int s = blockIdx.x;
    int bbase = s * 64;
    int tx = tid & 15, ty = tid >> 4;
    int row = ty * 8, col = tx * 4;
    float acc[8][4] = {};
    for (int bc = 0; bc < 64; bc += 32) {
        int b0 = bbase + bc;
#pragma unroll
        for (int p = 0; p < 4; p++) {
            int slot = tid + p * 256;
            int r = slot >> 3, c4 = (slot & 7) * 4;
            float4 a = *(const float4*)&g_ratio1[(size_t)r * BDIM + b0 + c4];
            As[c4 + 0][r] = a.x; As[c4 + 1][r] = a.y;
            As[c4 + 2][r] = a.z; As[c4 + 3][r] = a.w;
        }
#pragma unroll
        for (int p = 0; p < 2; p++) {
            int slot = tid + p * 256;
            int j = slot >> 3, c4 = (slot & 7) * 4;
            float4 t = *(const float4*)&theta1[(size_t)j * BDIM + b0 + c4];
            Bs[c4 + 0][j] = t.x; Bs[c4 + 1][j] = t.y;
            Bs[c4 + 2][j] = t.z; Bs[c4 + 3][j] = t.w;
        }
        __syncthreads();
#pragma unroll
        for (int c = 0; c < 32; c++) {
            float ra[8], rb[4];
#pragma unroll
            for (int i = 0; i < 8; i++) ra[i] = As[c][row + i];
#pragma unroll
            for (int j = 0; j < 4; j++) rb[j] = Bs[c][col + j];
#pragma unroll
            for (int i = 0; i < 8; i++)
#pragma unroll
                for (int j = 0; j < 4; j++) acc[i][j] += ra[i] * rb[j];
        }
        __syncthreads();
    }
    float* dst = &g_l1wp[(size_t)s * K0 * K1];
#pragma unroll
    for (int i = 0; i < 8; i++)
#pragma unroll
        for (int j = 0; j < 4; j++)
            dst[(size_t)(row + i) * K1 + col + j] = acc[i][j];
}

// Layer 1 counts: X2 = theta1 * (phi1^T @ ratio1), out (64, B), K=128
__global__ void k_l1x(const float* __restrict__ phi1,
                      const float* __restrict__ theta1) {
    __shared__ float As[32][64];    // [ii][k1]
    __shared__ float Bs[32][128];   // [ii][b]
    int tid = threadIdx.x;
    int b0 = blockIdx.x * 128;
    int tx = tid & 15, ty = tid >> 4;
    int row = ty * 4, col = tx * 8;   // row over k1 (64), col over b
    float acc[4][8] = {};
    for (int i0 = 0; i0 < K0; i0 += 32) {
#pragma unroll
        for (int p = 0; p < 2; p++) {
            int slot = tid + p * 256;
            int ii = slot >> 4, j4 = (slot & 15) * 4;
            *(float4*)&As[ii][j4] =
                *(const float4*)&phi1[(size_t)(i0 + ii) * K1 + j4];
        }
#pragma unroll
        for (int p = 0; p < 4; p++) {
            int slot = tid + p * 256;
            int ii = slot >> 5, j4 = (slot & 31) * 4;
            *(float4*)&Bs[ii][j4] =
                *(const float4*)&g_ratio1[(size_t)(i0 + ii) * BDIM + b0 + j4];
        }
        __syncthreads();
#pragma unroll
        for (int c = 0; c < 32; c++) {
            float ra[4], rb[8];
#pragma unroll
            for (int i = 0; i < 4; i++) ra[i] = As[c][row + i];
#pragma unroll
            for (int j = 0; j < 8; j++) rb[j] = Bs[c][col + j];
#pragma unroll
            for (int i = 0; i < 4; i++)
#pragma unroll
                for (int j = 0; j < 8; j++) acc[i][j] += ra[i] * rb[j];
        }
        __syncthreads();
    }
#pragma unroll
    for (int i = 0; i < 4; i++)
#pragma unroll
        for (int j = 0; j < 8; j++) {
            size_t idx = (size_t)(row + i) * BDIM + b0 + col + j;
            g_X2[idx] = theta1[idx] * acc[i][j];
        }
}

// Layer 1 TLASGR + simplex projection (one CTA, thread-per-column)
__global__ void k_l1tl(const float* __restrict__ phi1,
                       const float* __restrict__ noise1,
                       float* __restrict__ out) {
    __shared__ float sW[K0 * K1];
    int t = threadIdx.x;   // 64 columns
    float sw = 0.f, sp = 0.f, sn = 0.f;
    for (int i = 0; i < K0; i++) {
        int idx = i * K1 + t;
        float w = 0.f;
#pragma unroll
        for (int s = 0; s < 8; s++) w += g_l1wp[s * K0 * K1 + idx];
        float ph = phi1[idx];
        w *= ph;
        sW[idx] = w;
        sw += w; sp += ph; sn += sqrtf(ph) * noise1[idx];
    }
    float NDot   = 100.f * sw;
    float tmpsum = NDot + 0.1f * (float)K0;
    float inv_n  = 1.f / fmaxf(NDot, EPSV);
    float beta   = sqrtf(2.f * inv_n);
    float ssum   = sp + inv_n * (tmpsum - tmpsum * sp) + beta * sn;
    float c3     = ssum - 1.f;
    float psum = 0.f;
    for (int i = 0; i < K0; i++) {
        int idx = i * K1 + t;
        float ph  = phi1[idx];
        float tmp = 100.f * sW[idx] + 0.1f;
        float step = ph + inv_n * (tmp - tmpsum * ph)
                   + beta * sqrtf(ph) * noise1[idx];
        float p = fmaxf(EPSV, step - c3 * ph);
        sW[idx] = p;
        psum += p;
    }
    float pinv = 1.f / fmaxf(EPSV, psum);
    for (int i = 0; i < K0; i++)
        out[OFF1 + i * K1 + t] = sW[i * K1 + t] * pinv;
}

// ---------------------------------------------------------------------------
// Layer 2: ratio2 (64, B) with K=32; tiles 64x128
// ---------------------------------------------------------------------------
__global__ void k_l2ratio(const float* __restrict__ phi2,
                          const float* __restrict__ theta2) {
    __shared__ float As[32][68];
    __shared__ float Bs[32][128];
    int tid = threadIdx.x;
    int b0 = blockIdx.x * 128;
    int tx = tid & 15, ty = tid >> 4;
    int row = ty * 4, col = tx * 8;
    float acc[4][8] = {};
    {
#pragma unroll
        for (int p = 0; p < 2; p++) {
            int slot = tid + p * 256;
            int r = slot >> 3, c4 = (slot & 7) * 4;
            float4 a = *(const float4*)&phi2[(size_t)r * K2 + c4];
            As[c4 + 0][r] = a.x; As[c4 + 1][r] = a.y;
            As[c4 + 2][r] = a.z; As[c4 + 3][r] = a.w;
        }
#pragma unroll
        for (int p = 0; p < 4; p++) {
            int slot = tid + p * 256;
            int c = slot >> 5, j4 = (slot & 31) * 4;
            *(float4*)&Bs[c][j4] =
                *(const float4*)&theta2[(size_t)c * BDIM + b0 + j4];
        }
        __syncthreads();
#pragma unroll
        for (int c = 0; c < 32; c++) {
            float ra[4], rb[8];
#pragma unroll
            for (int i = 0; i < 4; i++) ra[i] = As[c][row + i];
#pragma unroll
            for (int j = 0; j < 8; j++) rb[j] = Bs[c][col + j];
#pragma unroll
            for (int i = 0; i < 4; i++)
#pragma unroll
                for (int j = 0; j < 8; j++) acc[i][j] += ra[i] * rb[j];
        }
    }
#pragma unroll
    for (int i = 0; i < 4; i++) {
        int v = row + i;
#pragma unroll
        for (int j = 0; j < 8; j++) {
            float d  = fmaxf(acc[i][j], EPSV);
            float xv = g_X2[(size_t)v * BDIM + b0 + col + j];
            g_ratio2[(size_t)v * BDIM + b0 + col + j] =
                digammaf_(d + xv) - digammaf_(d);
        }
    }
}

// Layer 2 WSZS partials: (64 x 32) = ratio2 @ theta2^T, split-K over b (8x64)
__global__ void k_l2wszs(const float* __restrict__ theta2) {
    __shared__ float As[32][68];
    __shared__ float Bs[32][36];
    int tid = threadIdx.x;
    int s = blockIdx.x;
    int bbase = s * 64;
    int tx = tid & 15, ty = tid >> 4;
    int row = ty * 4, col = tx * 2;
    float acc[4][2] = {};
    for (int bc = 0; bc < 64; bc += 32) {
        int b0 = bbase + bc;
#pragma unroll
        for (int p = 0; p < 2; p++) {
            int slot = tid + p * 256;
            int r = slot >> 3, c4 = (slot & 7) * 4;
            float4 a = *(const float4*)&g_ratio2[(size_t)r * BDIM + b0 + c4];
            As[c4 + 0][r] = a.x; As[c4 + 1][r] = a.y;
            As[c4 + 2][r] = a.z; As[c4 + 3][r] = a.w;
        }
        {
            int slot = tid;   // 256 slots = 32x8
            int j = slot >> 3, c4 = (slot & 7) * 4;
            float4 t = *(const float4*)&theta2[(size_t)j * BDIM + b0 + c4];
            Bs[c4 + 0][j] = t.x; Bs[c4 + 1][j] = t.y;
            Bs[c4 + 2][j] = t.z; Bs[c4 + 3][j] = t.w;
        }
        __syncthreads();
#pragma unroll
        for (int c = 0; c < 32; c++) {
            float ra[4], rb[2];
#pragma unroll
            for (int i = 0; i < 4; i++) ra[i] = As[c][row + i];
#pragma unroll
            for (int j = 0; j < 2; j++) rb[j] = Bs[c][col + j];
#pragma unroll
            for (int i = 0; i < 4; i++)
#pragma unroll
                for (int j = 0; j < 2; j++) acc[i][j] += ra[i] * rb[j];
        }
        __syncthreads();
    }
    float* dst = &g_l2wp[(size_t)s * K1 * K2];
#pragma unroll
    for (int i = 0; i < 4; i++)
#pragma unroll
        for (int j = 0; j < 2; j++)
            dst[(size_t)(row + i) * K2 + col + j] = acc[i][j];
}

// Layer 2 TLASGR (one CTA, 32 columns)
__global__ void k_l2tl(const float* __restrict__ phi2,
                       const float* __restrict__ noise2,
                       float* __restrict__ out) {
    __shared__ float sW[K1 * K2];
    int t = threadIdx.x;   // 32 columns
    float sw = 0.f, sp = 0.f, sn = 0.f;
    for (int i = 0; i < K1; i++) {
        int idx = i * K2 + t;
        float w = 0.f;
#pragma unroll
        for (int s = 0; s < 8; s++) w += g_l2wp[s * K1 * K2 + idx];
        float ph = phi2[idx];
        w *= ph;
        sW[idx] = w;
        sw += w; sp += ph; sn += sqrtf(ph) * noise2[idx];
    }
    float NDot   = 100.f * sw;
    float tmpsum = NDot + 0.1f * (float)K1;
    float inv_n  = 1.f / fmaxf(NDot, EPSV);
    float beta   = sqrtf(2.f * inv_n);
    float ssum   = sp + inv_n * (tmpsum - tmpsum * sp) + beta * sn;
    float c3     = ssum - 1.f;
    float psum = 0.f;
    for (int i = 0; i < K1; i++) {
        int idx = i * K2 + t;
        float ph  = phi2[idx];
        float tmp = 100.f * sW[idx] + 0.1f;
        float step = ph + inv_n * (tmp - tmpsum * ph)
                   + beta * sqrtf(ph) * noise2[idx];
        float p = fmaxf(EPSV, step - c3 * ph);
        sW[idx] = p;
        psum += p;
    }
    float pinv = 1.f / fmaxf(EPSV, psum);
    for (int i = 0; i < K1; i++)
        out[OFF2 + i * K2 + t] = sW[i * K2 + t] * pinv;
}

// ---------------------------------------------------------------------------
// Launcher
// ---------------------------------------------------------------------------
extern "C" void kernel_launch(void* const* d_in, const int* in_sizes, int n_in,
                              void* d_out, int out_size) {
    const float* x      = (const float*)d_in[0];
    const float* theta0 = (const float*)d_in[1];
    const float* theta1 = (const float*)d_in[2];
    const float* theta2 = (const float*)d_in[3];
    const float* phi0   = (const float*)d_in[4];
    const float* phi1   = (const float*)d_in[5];
    const float* phi2   = (const float*)d_in[6];
    const float* noise0 = (const float*)d_in[7];
    const float* noise1 = (const float*)d_in[8];
    const float* noise2 = (const float*)d_in[9];
    float* out = (float*)d_out;

    // ---- layer 0 ----
    k_transpose<<<dim3((VDIM + 31) / 32, BDIM / 32), dim3(32, 8)>>>(x);
    k_ratio0<<<dim3((VDIM + 127) / 128, BDIM / 128), 256>>>(phi0, theta0);
    k_wszs0<<<dim3((VDIM + 127) / 128, 1), 256>>>(phi0, theta0);
    k_x1part<<<dim3(BDIM / 128, NS0), 256>>>(phi0);
    k_x1red<<<64, 1024>>>(theta0);
    k_colA<<<NCH, K0>>>(phi0, noise0);
    k_colB<<<1, K0>>>();
    k_p0<<<NCH, K0>>>(phi0, noise0, out);
    k_psumfin<<<1, K0>>>();
    k_norm0<<<3750, 1024>>>(out);

    // ---- layer 1 ----
    k_l1ratio<<<BDIM / 128, 256>>>(phi1, theta1);
    k_l1wszs<<<8, 256>>>(theta1);
    k_l1x<<<BDIM / 128, 256>>>(phi1, theta1);
    k_l1tl<<<1, K1>>>(phi1, noise1, out);

    // ---- layer 2 ----
    k_l2ratio<<<BDIM / 128, 256>>>(phi2, theta2);
    k_l2wszs<<<8, 256>>>(theta2);
    k_l2tl<<<1, K2>>>(phi2, noise2, out);
}

// round 5
// speedup vs baseline: 1.0986x; 1.0986x over previous
#include <cuda_runtime.h>
#include <math.h>
#include <stdint.h>

// ---------------------------------------------------------------------------
// Problem constants
// ---------------------------------------------------------------------------
#define EPSV 2.2e-10f
#define VDIM 30000
#define BDIM 512
#define K0 128
#define K1 64
#define K2 32

#define OFF1 (VDIM * K0)            // 3,840,000
#define OFF2 (OFF1 + K0 * K1)       // 3,848,192

#define NS0 60                      // splits for phi0^T @ ratio0 (30000/60 = 500)
#define VCH 500
#define NCH 120                     // row chunks for column reductions (30000/120=250)
#define RCH 250

// ---------------------------------------------------------------------------
// Device scratch (no allocations allowed)
// ---------------------------------------------------------------------------
__device__ float g_xT[VDIM * BDIM];
__device__ float g_ratio0[VDIM * BDIM];
__device__ float g_WSZS0[VDIM * K0];
__device__ float g_x1part[NS0 * K0 * BDIM];
__device__ float g_X1[K0 * BDIM];
__device__ float g_c0part[NCH * 3 * K0];
__device__ float g_c0[4 * K0];
__device__ float g_ppart[NCH * K0];
__device__ float g_pinv0[K0];
__device__ float g_den1[K0 * BDIM];
__device__ float g_ratio1[K0 * BDIM];
__device__ float g_l1wp[8 * K0 * K1];
__device__ float g_X2[K1 * BDIM];
__device__ float g_den2[K1 * BDIM];
__device__ float g_ratio2[K1 * BDIM];
__device__ float g_l2wp[8 * K1 * K2];

// ---------------------------------------------------------------------------
// fp32 digamma (avoid FP64)
// ---------------------------------------------------------------------------
__device__ __forceinline__ float digammaf_(float x) {
    float r = 0.f;
    while (x < 6.f) { r -= 1.f / x; x += 1.f; }
    float inv  = 1.f / x;
    float inv2 = inv * inv;
    float s = logf(x) - 0.5f * inv
        - inv2 * (0.083333333333f
        - inv2 * (0.008333333333f
        - inv2 * (0.003968253968f
        - inv2 * (0.004166666667f
        - inv2 * 0.007575757576f))));
    return r + s;
}

// ---------------------------------------------------------------------------
// 1) transpose x (B,V) -> g_xT (V,B)
// ---------------------------------------------------------------------------
__global__ void k_transpose(const float* __restrict__ x) {
    __shared__ float tile[32][33];
    int v0 = blockIdx.x * 32, b0 = blockIdx.y * 32;
    int tx = threadIdx.x, ty = threadIdx.y;   // (32, 8)
#pragma unroll
    for (int i = 0; i < 32; i += 8) {
        int v = v0 + tx, b = b0 + ty + i;
        tile[ty + i][tx] = (v < VDIM) ? x[(size_t)b * VDIM + v] : 0.f;
    }
    __syncthreads();
#pragma unroll
    for (int i = 0; i < 32; i += 8) {
        int v = v0 + ty + i, b = b0 + tx;
        if (v < VDIM) g_xT[(size_t)v * BDIM + b] = tile[tx][ty + i];
    }
}

// ---------------------------------------------------------------------------
// 2) ratio0 = xT / max(phi0 @ theta0, EPS)
//    128x128 tiles, K=128; single static smem buffer + register prefetch:
//    next tile's LDGs issue before the FFMA block, lands after it.
// ---------------------------------------------------------------------------
__global__ void __launch_bounds__(256, 2)
k_ratio0(const float* __restrict__ phi0, const float* __restrict__ theta0) {
    __shared__ float As[32 * 132];   // [k][v] transposed
    __shared__ float Bs[32 * 128];   // [k][b] direct
    int tid = threadIdx.x;
    int v0 = blockIdx.x * 128, b0 = blockIdx.y * 128;
    int tx = tid & 15, ty = tid >> 4;
    int row = ty * 8, col = tx * 8;
    float4 areg[4], breg[4];

    // prologue: fetch k-step 0 into regs
#pragma unroll
    for (int p = 0; p < 4; p++) {
        int slot = tid + p * 256;
        int r = slot >> 3, c4 = (slot & 7) * 4;
        areg[p] = make_float4(0.f, 0.f, 0.f, 0.f);
        if (v0 + r < VDIM)
            areg[p] = *(const float4*)&phi0[(size_t)(v0 + r) * K0 + c4];
        int c = slot >> 5, j4 = (slot & 31) * 4;
        breg[p] = *(const float4*)&theta0[(size_t)c * BDIM + b0 + j4];
    }
#pragma unroll
    for (int p = 0; p < 4; p++) {
        int slot = tid + p * 256;
        int r = slot >> 3, c4 = (slot & 7) * 4;
        As[(c4 + 0) * 132 + r] = areg[p].x;
        As[(c4 + 1) * 132 + r] = areg[p].y;
        As[(c4 + 2) * 132 + r] = areg[p].z;
        As[(c4 + 3) * 132 + r] = areg[p].w;
        int c = slot >> 5, j4 = (slot & 31) * 4;
        *(float4*)&Bs[c * 128 + j4] = breg[p];
    }
    __syncthreads();

    float acc[8][8] = {};
#pragma unroll 1
    for (int s = 0; s < 4; s++) {
        if (s < 3) {   // prefetch next k-step into regs (hidden under compute)
            int k0 = (s + 1) * 32;
#pragma unroll
            for (int p = 0; p < 4; p++) {
                int slot = tid + p * 256;
                int r = slot >> 3, c4 = (slot & 7) * 4;
                areg[p] = make_float4(0.f, 0.f, 0.f, 0.f);
                if (v0 + r < VDIM)
                    areg[p] = *(const float4*)&phi0[(size_t)(v0 + r) * K0 + k0 + c4];
                int c = slot >> 5, j4 = (slot & 31) * 4;
                breg[p] = *(const float4*)&theta0[(size_t)(k0 + c) * BDIM + b0 + j4];
            }
        }
#pragma unroll
        for (int c = 0; c < 32; c++) {
            float4 a0 = *(const float4*)&As[c * 132 + row];
            float4 a1 = *(const float4*)&As[c * 132 + row + 4];
            float4 bv0 = *(const float4*)&Bs[c * 128 + col];
            float4 bv1 = *(const float4*)&Bs[c * 128 + col + 4];
            float ra[8] = {a0.x, a0.y, a0.z, a0.w, a1.x, a1.y, a1.z, a1.w};
            float rb[8] = {bv0.x, bv0.y, bv0.z, bv0.w, bv1.x, bv1.y, bv1.z, bv1.w};
#pragma unroll
            for (int i = 0; i < 8; i++)
#pragma unroll
                for (int j = 0; j < 8; j++) acc[i][j] += ra[i] * rb[j];
        }
        __syncthreads();            // all reads of smem done
        if (s < 3) {
#pragma unroll
            for (int p = 0; p < 4; p++) {
                int slot = tid + p * 256;
                int r = slot >> 3, c4 = (slot & 7) * 4;
                As[(c4 + 0) * 132 + r] = areg[p].x;
                As[(c4 + 1) * 132 + r] = areg[p].y;
                As[(c4 + 2) * 132 + r] = areg[p].z;
                As[(c4 + 3) * 132 + r] = areg[p].w;
                int c = slot >> 5, j4 = (slot & 31) * 4;
                *(float4*)&Bs[c * 128 + j4] = breg[p];
            }
            __syncthreads();        // tile visible to all
        }
    }
#pragma unroll
    for (int i = 0; i < 8; i++) {
        int v = v0 + row + i;
        if (v >= VDIM) break;
#pragma unroll
        for (int j = 0; j < 8; j += 4) {
            float4 xv = *(const float4*)&g_xT[(size_t)v * BDIM + b0 + col + j];
            float4 o;
            o.x = xv.x / fmaxf(acc[i][j + 0], EPSV);
            o.y = xv.y / fmaxf(acc[i][j + 1], EPSV);
            o.z = xv.z / fmaxf(acc[i][j + 2], EPSV);
            o.w = xv.w / fmaxf(acc[i][j + 3], EPSV);
            *(float4*)&g_ratio0[(size_t)v * BDIM + b0 + col + j] = o;
        }
    }
}

// ---------------------------------------------------------------------------
// 3) WSZS0 = phi0 * (ratio0 @ theta0^T)  128(v)x128(k) tile, K=512 over b
//    single buffer + register prefetch; both operands transposed in smem
// ---------------------------------------------------------------------------
__global__ void __launch_bounds__(256, 2)
k_wszs0(const float* __restrict__ phi0, const float* __restrict__ theta0) {
    __shared__ float As[32 * 132];   // [b][v]
    __shared__ float Bs[32 * 132];   // [b][k]
    int tid = threadIdx.x;
    int v0 = blockIdx.x * 128;
    int tx = tid & 15, ty = tid >> 4;
    int row = ty * 8, col = tx * 8;
    float4 areg[4], breg[4];

#pragma unroll
    for (int p = 0; p < 4; p++) {
        int slot = tid + p * 256;
        int r = slot >> 3, c4 = (slot & 7) * 4;
        areg[p] = make_float4(0.f, 0.f, 0.f, 0.f);
        if (v0 + r < VDIM)
            areg[p] = *(const float4*)&g_ratio0[(size_t)(v0 + r) * BDIM + c4];
        breg[p] = *(const float4*)&theta0[(size_t)r * BDIM + c4];
    }
#pragma unroll
    for (int p = 0; p < 4; p++) {
        int slot = tid + p * 256;
        int r = slot >> 3, c4 = (slot & 7) * 4;
        As[(c4 + 0) * 132 + r] = areg[p].x; As[(c4 + 1) * 132 + r] = areg[p].y;
        As[(c4 + 2) * 132 + r] = areg[p].z; As[(c4 + 3) * 132 + r] = areg[p].w;
        Bs[(c4 + 0) * 132 + r] = breg[p].x; Bs[(c4 + 1) * 132 + r] = breg[p].y;
        Bs[(c4 + 2) * 132 + r] = breg[p].z; Bs[(c4 + 3) * 132 + r] = breg[p].w;
    }
    __syncthreads();

    float acc[8][8] = {};
#pragma unroll 1
    for (int s = 0; s < 16; s++) {
        if (s < 15) {
            int b0 = (s + 1) * 32;
#pragma unroll
            for (int p = 0; p < 4; p++) {
                int slot = tid + p * 256;
                int r = slot >> 3, c4 = (slot & 7) * 4;
                areg[p] = make_float4(0.f, 0.f, 0.f, 0.f);
                if (v0 + r < VDIM)
                    areg[p] = *(const float4*)&g_ratio0[(size_t)(v0 + r) * BDIM + b0 + c4];
                breg[p] = *(const float4*)&theta0[(size_t)r * BDIM + b0 + c4];
            }
        }
#pragma unroll
        for (int c = 0; c < 32; c++) {
            float4 a0 = *(const float4*)&As[c * 132 + row];
            float4 a1 = *(const float4*)&As[c * 132 + row + 4];
            float4 bv0 = *(const float4*)&Bs[c * 132 + col];
            float4 bv1 = *(const float4*)&Bs[c * 132 + col + 4];
            float ra[8] = {a0.x, a0.y, a0.z, a0.w, a1.x, a1.y, a1.z, a1.w};
            float rb[8] = {bv0.x, bv0.y, bv0.z, bv0.w, bv1.x, bv1.y, bv1.z, bv1.w};
#pragma unroll
            for (int i = 0; i < 8; i++)
#pragma unroll
                for (int j = 0; j < 8; j++) acc[i][j] += ra[i] * rb[j];
        }
        __syncthreads();
        if (s < 15) {
#pragma unroll
            for (int p = 0; p < 4; p++) {
                int slot = tid + p * 256;
                int r = slot >> 3, c4 = (slot & 7) * 4;
                As[(c4 + 0) * 132 + r] = areg[p].x; As[(c4 + 1) * 132 + r] = areg[p].y;
                As[(c4 + 2) * 132 + r] = areg[p].z; As[(c4 + 3) * 132 + r] = areg[p].w;
                Bs[(c4 + 0) * 132 + r] = breg[p].x; Bs[(c4 + 1) * 132 + r] = breg[p].y;
                Bs[(c4 + 2) * 132 + r] = breg[p].z; Bs[(c4 + 3) * 132 + r] = breg[p].w;
            }
            __syncthreads();
        }
    }
#pragma unroll
    for (int i = 0; i < 8; i++) {
        int v = v0 + row + i;
        if (v >= VDIM) break;
#pragma unroll
        for (int j = 0; j < 8; j += 4) {
            float4 ph = *(const float4*)&phi0[(size_t)v * K0 + col + j];
            float4 o;
            o.x = ph.x * acc[i][j + 0];
            o.y = ph.y * acc[i][j + 1];
            o.z = ph.z * acc[i][j + 2];
            o.w = ph.w * acc[i][j + 3];
            *(float4*)&g_WSZS0[(size_t)v * K0 + col + j] = o;
        }
    }
}

// ---------------------------------------------------------------------------
// 4) split-K partials of phi0^T @ ratio0 (deterministic); single buffer +
//    register prefetch; both tiles direct layout
// ---------------------------------------------------------------------------
__global__ void __launch_bounds__(256, 2)
k_x1part(const float* __restrict__ phi0) {
    __shared__ float As[32 * 128];   // [vv][k]
    __shared__ float Bs[32 * 128];   // [vv][b]
    int tid = threadIdx.x;
    int b0 = blockIdx.x * 128;
    int s_ = blockIdx.y;
    int vbeg = s_ * VCH, vend = vbeg + VCH;
    int tx = tid & 15, ty = tid >> 4;
    int row = ty * 8, col = tx * 8;
    const int nsteps = (VCH + 31) / 32;   // 16
    float4 areg[4], breg[4];

#pragma unroll
    for (int p = 0; p < 4; p++) {
        int slot = tid + p * 256;
        int vv = slot >> 5, j4 = (slot & 31) * 4;
        int vg = vbeg + vv;
        areg[p] = make_float4(0.f, 0.f, 0.f, 0.f);
        breg[p] = make_float4(0.f, 0.f, 0.f, 0.f);
        if (vg < vend) {
            areg[p] = *(const float4*)&phi0[(size_t)vg * K0 + j4];
            breg[p] = *(const float4*)&g_ratio0[(size_t)vg * BDIM + b0 + j4];
        }
    }
#pragma unroll
    for (int p = 0; p < 4; p++) {
        int slot = tid + p * 256;
        int vv = slot >> 5, j4 = (slot & 31) * 4;
        *(float4*)&As[vv * 128 + j4] = areg[p];
        *(float4*)&Bs[vv * 128 + j4] = breg[p];
    }
    __syncthreads();

    float acc[8][8] = {};
#pragma unroll 1
    for (int s = 0; s < nsteps; s++) {
        if (s + 1 < nsteps) {
            int v0 = vbeg + (s + 1) * 32;
#pragma unroll
            for (int p = 0; p < 4; p++) {
                int slot = tid + p * 256;
                int vv = slot >> 5, j4 = (slot & 31) * 4;
                int vg = v0 + vv;
                areg[p] = make_float4(0.f, 0.f, 0.f, 0.f);
                breg[p] = make_float4(0.f, 0.f, 0.f, 0.f);
                if (vg < vend) {
                    areg[p] = *(const float4*)&phi0[(size_t)vg * K0 + j4];
                    breg[p] = *(const float4*)&g_ratio0[(size_t)vg * BDIM + b0 + j4];
                }
            }
        }
#pragma unroll
        for (int c = 0; c < 32; c++) {
            float4 a0 = *(const float4*)&As[c * 128 + row];
            float4 a1 = *(const float4*)&As[c * 128 + row + 4];
            float4 bv0 = *(const float4*)&Bs[c * 128 + col];
            float4 bv1 = *(const float4*)&Bs[c * 128 + col + 4];
            float ra[8] = {a0.x, a0.y, a0.z, a0.w, a1.x, a1.y, a1.z, a1.w};
            float rb[8] = {bv0.x, bv0.y, bv0.z, bv0.w, bv1.x, bv1.y, bv1.z, bv1.w};
#pragma unroll
            for (int i = 0; i < 8; i++)
#pragma unroll
                for (int j = 0; j < 8; j++) acc[i][j] += ra[i] * rb[j];
        }
        __syncthreads();
        if (s + 1 < nsteps) {
#pragma unroll
            for (int p = 0; p < 4; p++) {
                int slot = tid + p * 256;
                int vv = slot >> 5, j4 = (slot & 31) * 4;
                *(float4*)&As[vv * 128 + j4] = areg[p];
                *(float4*)&Bs[vv * 128 + j4] = breg[p];
            }
            __syncthreads();
        }
    }
    float* dst = &g_x1part[(size_t)s_ * K0 * BDIM];
#pragma unroll
    for (int i = 0; i < 8; i++)
#pragma unroll
        for (int j = 0; j < 8; j += 4)
            *(float4*)&dst[(size_t)(row + i) * BDIM + b0 + col + j] =
                make_float4(acc[i][j], acc[i][j + 1], acc[i][j + 2], acc[i][j + 3]);
}

// 5) reduce partials, multiply by theta0 -> X1
__global__ void k_x1red(const float* __restrict__ theta0) {
    int idx = blockIdx.x * 1024 + threadIdx.x;
    float s = 0.f;
#pragma unroll 10
    for (int p = 0; p < NS0; p++) s += g_x1part[(size_t)p * K0 * BDIM + idx];
    g_X1[idx] = theta0[idx] * s;
}

// ---------------------------------------------------------------------------
// 6/7) column stats for layer-0 TLASGR
// ---------------------------------------------------------------------------
__global__ void k_colA(const float* __restrict__ phi0,
                       const float* __restrict__ noise0) {
    int t = threadIdx.x;
    int ch = blockIdx.x;
    float sw = 0.f, sp = 0.f, sn = 0.f;
    int vbeg = ch * RCH;
#pragma unroll 5
    for (int r = 0; r < RCH; r++) {
        size_t idx = (size_t)(vbeg + r) * K0 + t;
        sw += g_WSZS0[idx];
        float ph = phi0[idx];
        sp += ph;
        sn += sqrtf(ph) * noise0[idx];
    }
    g_c0part[ch * 384 + t]        = sw;
    g_c0part[ch * 384 + 128 + t]  = sp;
    g_c0part[ch * 384 + 256 + t]  = sn;
}

__global__ void k_colB() {
    int t = threadIdx.x;
    float sw = 0.f, sp = 0.f, sn = 0.f;
#pragma unroll 10
    for (int ch = 0; ch < NCH; ch++) {
        sw += g_c0part[ch * 384 + t];
        sp += g_c0part[ch * 384 + 128 + t];
        sn += g_c0part[ch * 384 + 256 + t];
    }
    float NDot   = 100.f * sw;
    float tmpsum = NDot + 0.1f * (float)VDIM;
    float inv_n  = 1.f / fmaxf(NDot, EPSV);
    float beta   = sqrtf(2.f * inv_n);
    float ssum   = sp + inv_n * (tmpsum - tmpsum * sp) + beta * sn;
    g_c0[t]           = inv_n;
    g_c0[128 + t]     = beta;
    g_c0[256 + t]     = tmpsum;
    g_c0[384 + t]     = ssum - 1.f;
}

// 8) p = max(EPS, step - (ssum-1)*phi); write + per-chunk psum
__global__ void k_p0(const float* __restrict__ phi0,
                     const float* __restrict__ noise0,
                     float* __restrict__ out) {
    int t = threadIdx.x;
    int ch = blockIdx.x;
    float inv_n = g_c0[t], beta = g_c0[128 + t];
    float tmpsum = g_c0[256 + t], c3 = g_c0[384 + t];
    float psum = 0.f;
    int vbeg = ch * RCH;
#pragma unroll 5
    for (int r = 0; r < RCH; r++) {
        size_t idx = (size_t)(vbeg + r) * K0 + t;
        float ph  = phi0[idx];
        float tmp = 100.f * g_WSZS0[idx] + 0.1f;
        float step = ph + inv_n * (tmp - tmpsum * ph)
                   + beta * sqrtf(ph) * noise0[idx];
        float p = fmaxf(EPSV, step - c3 * ph);
        out[idx] = p;
        psum += p;
    }
    g_ppart[ch * K0 + t] = psum;
}

__global__ void k_psumfin() {
    int t = threadIdx.x;
    float s = 0.f;
#pragma unroll 10
    for (int ch = 0; ch < NCH; ch++) s += g_ppart[ch * K0 + t];
    g_pinv0[t] = 1.f / fmaxf(EPSV, s);
}

__global__ void k_norm0(float* __restrict__ out) {
    int idx = blockIdx.x * 1024 + threadIdx.x;
    out[idx] *= g_pinv0[idx & 127];
}

// ---------------------------------------------------------------------------
// Layer 1: denom = phi1@theta1 (128x512, K=64), then elementwise digamma
// ---------------------------------------------------------------------------
__global__ void __launch_bounds__(256)
k_l1denom(const float* __restrict__ phi1, const float* __restrict__ theta1) {
    __shared__ float As[32][132];
    __shared__ float Bs[32][128];
    int tid = threadIdx.x;
    int b0 = blockIdx.x * 128;
    int tx = tid & 15, ty = tid >> 4;
    int row = ty * 8, col = tx * 8;
    float acc[8][8] = {};
    for (int k0 = 0; k0 < K1; k0 += 32) {
#pragma unroll
        for (int p = 0; p < 4; p++) {
            int slot = tid + p * 256;
            int r = slot >> 3, c4 = (slot & 7) * 4;
            float4 a = *(const float4*)&phi1[(size_t)r * K1 + k0 + c4];
            As[c4 + 0][r] = a.x; As[c4 + 1][r] = a.y;
            As[c4 + 2][r] = a.z; As[c4 + 3][r] = a.w;
        }
#pragma unroll
        for (int p = 0; p < 4; p++) {
            int slot = tid + p * 256;
            int c = slot >> 5, j4 = (slot & 31) * 4;
            *(float4*)&Bs[c][j4] =
                *(const float4*)&theta1[(size_t)(k0 + c) * BDIM + b0 + j4];
        }
        __syncthreads();
#pragma unroll
        for (int c = 0; c < 32; c++) {
            float4 a0 = *(const float4*)&As[c][row];
            float4 a1 = *(const float4*)&As[c][row + 4];
            float4 bv0 = *(const float4*)&Bs[c][col];
            float4 bv1 = *(const float4*)&Bs[c][col + 4];
            float ra[8] = {a0.x, a0.y, a0.z, a0.w, a1.x, a1.y, a1.z, a1.w};
            float rb[8] = {bv0.x, bv0.y, bv0.z, bv0.w, bv1.x, bv1.y, bv1.z, bv1.w};
#pragma unroll
            for (int i = 0; i < 8; i++)
#pragma unroll
                for (int j = 0; j < 8; j++) acc[i][j] += ra[i] * rb[j];
        }
        __syncthreads();
    }
#pragma unroll
    for (int i = 0; i < 8; i++)
#pragma unroll
        for (int j = 0; j < 8; j++)
            g_den1[(size_t)(row + i) * BDIM + b0 + col + j] = acc[i][j];
}

__global__ void k_l1dig() {
    int idx = blockIdx.x * 256 + threadIdx.x;   // 256 blocks -> 65536
    float d = fmaxf(g_den1[idx], EPSV);
    g_ratio1[idx] = digammaf_(d + g_X1[idx]) - digammaf_(d);
}

// Layer 1 WSZS partials: (128 x 64) = ratio1 @ theta1^T, split over b (8x64)
__global__ void k_l1wszs(const float* __restrict__ theta1) {
    __shared__ float As[32][132];
    __shared__ float Bs[32][68];
    int tid = threadIdx.x;
    int s = blockIdx.x;
    int bbase = s * 64;
    int tx = tid & 15, ty = tid >> 4;
    int row = ty * 8, col = tx * 4;
    float acc[8][4] = {};
    for (int bc = 0; bc < 64; bc += 32) {
        int b0 = bbase + bc;
#pragma unroll
        for (int p = 0; p < 4; p++) {
            int slot = tid + p * 256;
            int r = slot >> 3, c4 = (slot & 7) * 4;
            float4 a = *(const float4*)&g_ratio1[(size_t)r * BDIM + b0 + c4];
            As[c4 + 0][r] = a.x; As[c4 + 1][r] = a.y;
            As[c4 + 2][r] = a.z; As[c4 + 3][r] = a.w;
        }
#pragma unroll
        for (int p = 0; p < 2; p++) {
            int slot = tid + p * 256;
            int j = slot >> 3, c4 = (slot & 7) * 4;
            float4 t = *(const float4*)&theta1[(size_t)j * BDIM + b0 + c4];
            Bs[c4 + 0][j] = t.x; Bs[c4 + 1][j] = t.y;
            Bs[c4 + 2][j] = t.z; Bs[c4 + 3][j] = t.w;
        }
        __syncthreads();
#pragma unroll
        for (int c = 0; c < 32; c++) {
            float ra[8], rb[4];
#pragma unroll
            for (int i = 0; i < 8; i++) ra[i] = As[c][row + i];
#pragma unroll
            for (int j = 0; j < 4; j++) rb[j] = Bs[c][col + j];
#pragma unroll
            for (int i = 0; i < 8; i++)
#pragma unroll
                for (int j = 0; j < 4; j++) acc[i][j] += ra[i] * rb[j];
        }
        __syncthreads();
    }
    float* dst = &g_l1wp[(size_t)s * K0 * K1];
#pragma unroll
    for (int i = 0; i < 8; i++)
#pragma unroll
        for (int j = 0; j < 4; j++)
            dst[(size_t)(row + i) * K1 + col + j] = acc[i][j];
}

// Layer 1 counts: X2 = theta1 * (phi1^T @ ratio1), out (64, B), K=128
__global__ void k_l1x(const float* __restrict__ phi1,
                      const float* __restrict__ theta1) {
    __shared__ float As[32][64];
    __shared__ float Bs[32][128];
    int tid = threadIdx.x;
    int b0 = blockIdx.x * 128;
    int tx = tid & 15, ty = tid >> 4;
    int row = ty * 4, col = tx * 8;
    float acc[4][8] = {};
    for (int i0 = 0; i0 < K0; i0 += 32) {
#pragma unroll
        for (int p = 0; p < 2; p++) {
            int slot = tid + p * 256;
            int ii = slot >> 4, j4 = (slot & 15) * 4;
            *(float4*)&As[ii][j4] =
                *(const float4*)&phi1[(size_t)(i0 + ii) * K1 + j4];
        }
#pragma unroll
        for (int p = 0; p < 4; p++) {
            int slot = tid + p * 256;
            int ii = slot >> 5, j4 = (slot & 31) * 4;
            *(float4*)&Bs[ii][j4] =
                *(const float4*)&g_ratio1[(size_t)(i0 + ii) * BDIM + b0 + j4];
        }
        __syncthreads();
#pragma unroll
        for (int c = 0; c < 32; c++) {
            float ra[4], rb[8];
#pragma unroll
            for (int i = 0; i < 4; i++) ra[i] = As[c][row + i];
#pragma unroll
            for (int j = 0; j < 8; j++) rb[j] = Bs[c][col + j];
#pragma unroll
            for (int i = 0; i < 4; i++)
#pragma unroll
                for (int j = 0; j < 8; j++) acc[i][j] += ra[i] * rb[j];
        }
        __syncthreads();
    }
#pragma unroll
    for (int i = 0; i < 4; i++)
#pragma unroll
        for (int j = 0; j < 8; j++) {
            size_t idx = (size_t)(row + i) * BDIM + b0 + col + j;
            g_X2[idx] = theta1[idx] * acc[i][j];
        }
}

// Layer 1 TLASGR + simplex projection (one CTA, thread-per-column)
__global__ void k_l1tl(const float* __restrict__ phi1,
                       const float* __restrict__ noise1,
                       float* __restrict__ out) {
    __shared__ float sW[K0 * K1];
    int t = threadIdx.x;
    float sw = 0.f, sp = 0.f, sn = 0.f;
    for (int i = 0; i < K0; i++) {
        int idx = i * K1 + t;
        float w = 0.f;
#pragma unroll
        for (int s = 0; s < 8; s++) w += g_l1wp[s * K0 * K1 + idx];
        float ph = phi1[idx];
        w *= ph;
        sW[idx] = w;
        sw += w; sp += ph; sn += sqrtf(ph) * noise1[idx];
    }
    float NDot   = 100.f * sw;
    float tmpsum = NDot + 0.1f * (float)K0;
    float inv_n  = 1.f / fmaxf(NDot, EPSV);
    float beta   = sqrtf(2.f * inv_n);
    float ssum   = sp + inv_n * (tmpsum - tmpsum * sp) + beta * sn;
    float c3     = ssum - 1.f;
    float psum = 0.f;
    for (int i = 0; i < K0; i++) {
        int idx = i * K1 + t;
        float ph  = phi1[idx];
        float tmp = 100.f * sW[idx] + 0.1f;
        float step = ph + inv_n * (tmp - tmpsum * ph)
                   + beta * sqrtf(ph) * noise1[idx];
        float p = fmaxf(EPSV, step - c3 * ph);
        sW[idx] = p;
        psum += p;
    }
    float pinv = 1.f / fmaxf(EPSV, psum);
    for (int i = 0; i < K0; i++)
        out[OFF1 + i * K1 + t] = sW[i * K1 + t] * pinv;
}

// ---------------------------------------------------------------------------
// Layer 2: denom (64,B) K=32, then digamma
// ---------------------------------------------------------------------------
__global__ void k_l2denom(const float* __restrict__ phi2,
                          const float* __restrict__ theta2) {
    __shared__ float As[32][68];
    __shared__ float Bs[32][128];
    int tid = threadIdx.x;
    int b0 = blockIdx.x * 128;
    int tx = tid & 15, ty = tid >> 4;
    int row = ty * 4, col = tx * 8;
    float acc[4][8] = {};
    {
#pragma unroll
        for (int p = 0; p < 2; p++) {
            int slot = tid + p * 256;
            int r = slot >> 3, c4 = (slot & 7) * 4;
            float4 a = *(const float4*)&phi2[(size_t)r * K2 + c4];
            As[c4 + 0][r] = a.x; As[c4 + 1][r] = a.y;
            As[c4 + 2][r] = a.z; As[c4 + 3][r] = a.w;
        }
#pragma unroll
        for (int p = 0; p < 4; p++) {
            int slot = tid + p * 256;
            int c = slot >> 5, j4 = (slot & 31) * 4;
            *(float4*)&Bs[c][j4] =
                *(const float4*)&theta2[(size_t)c * BDIM + b0 + j4];
        }
        __syncthreads();
#pragma unroll
        for (int c = 0; c < 32; c++) {
            float ra[4], rb[8];
#pragma unroll
            for (int i = 0; i < 4; i++) ra[i] = As[c][row + i];
#pragma unroll
            for (int j = 0; j < 8; j++) rb[j] = Bs[c][col + j];
#pragma unroll
            for (int i = 0; i < 4; i++)
#pragma unroll
                for (int j = 0; j < 8; j++) acc[i][j] += ra[i] * rb[j];
        }
    }
#pragma unroll
    for (int i = 0; i < 4; i++)
#pragma unroll
        for (int j = 0; j < 8; j++)
            g_den2[(size_t)(row + i) * BDIM + b0 + col + j] = acc[i][j];
}

__global__ void k_l2dig() {
    int idx = blockIdx.x * 256 + threadIdx.x;   // 128 blocks -> 32768
    float d = fmaxf(g_den2[idx], EPSV);
    g_ratio2[idx] = digammaf_(d + g_X2[idx]) - digammaf_(d);
}

// Layer 2 WSZS partials: (64 x 32) = ratio2 @ theta2^T, split over b (8x64)
__global__ void k_l2wszs(const float* __restrict__ theta2) {
    __shared__ float As[32][68];
    __shared__ float Bs[32][36];
    int tid = threadIdx.x;
    int s = blockIdx.x;
    int bbase = s * 64;
    int tx = tid & 15, ty = tid >> 4;
    int row = ty * 4, col = tx * 2;
    float acc[4][2] = {};
    for (int bc = 0; bc < 64; bc += 32) {
        int b0 = bbase + bc;
#pragma unroll
        for (int p = 0; p < 2; p++) {
            int slot = tid + p * 256;
            int r = slot >> 3, c4 = (slot & 7) * 4;
            float4 a = *(const float4*)&g_ratio2[(size_t)r * BDIM + b0 + c4];
            As[c4 + 0][r] = a.x; As[c4 + 1][r] = a.y;
            As[c4 + 2][r] = a.z; As[c4 + 3][r] = a.w;
        }
        {
            int slot = tid;
            int j = slot >> 3, c4 = (slot & 7) * 4;
            float4 t = *(const float4*)&theta2[(size_t)j * BDIM + b0 + c4];
            Bs[c4 + 0][j] = t.x; Bs[c4 + 1][j] = t.y;
            Bs[c4 + 2][j] = t.z; Bs[c4 + 3][j] = t.w;
        }
        __syncthreads();
#pragma unroll
        for (int c = 0; c < 32; c++) {
            float ra[4], rb[2];
#pragma unroll
            for (int i = 0; i < 4; i++) ra[i] = As[c][row + i];
#pragma unroll
            for (int j = 0; j < 2; j++) rb[j] = Bs[c][col + j];
#pragma unroll
            for (int i = 0; i < 4; i++)
#pragma unroll
                for (int j = 0; j < 2; j++) acc[i][j] += ra[i] * rb[j];
        }
        __syncthreads();
    }
    float* dst = &g_l2wp[(size_t)s * K1 * K2];
#pragma unroll
    for (int i = 0; i < 4; i++)
#pragma unroll
        for (int j = 0; j < 2; j++)
            dst[(size_t)(row + i) * K2 + col + j] = acc[i][j];
}

// Layer 2 TLASGR (one CTA, 32 columns)
__global__ void k_l2tl(const float* __restrict__ phi2,
                       const float* __restrict__ noise2,
                       float* __restrict__ out) {
    __shared__ float sW[K1 * K2];
    int t = threadIdx.x;
    float sw = 0.f, sp = 0.f, sn = 0.f;
    for (int i = 0; i < K1; i++) {
        int idx = i * K2 + t;
        float w = 0.f;
#pragma unroll
        for (int s = 0; s < 8; s++) w += g_l2wp[s * K1 * K2 + idx];
        float ph = phi2[idx];
        w *= ph;
        sW[idx] = w;
        sw += w; sp += ph; sn += sqrtf(ph) * noise2[idx];
    }
    float NDot   = 100.f * sw;
    float tmpsum = NDot + 0.1f * (float)K1;
    float inv_n  = 1.f / fmaxf(NDot, EPSV);
    float beta   = sqrtf(2.f * inv_n);
    float ssum   = sp + inv_n * (tmpsum - tmpsum * sp) + beta * sn;
    float c3     = ssum - 1.f;
    float psum = 0.f;
    for (int i = 0; i < K1; i++) {
        int idx = i * K2 + t;
        float ph  = phi2[idx];
        float tmp = 100.f * sW[idx] + 0.1f;
        float step = ph + inv_n * (tmp - tmpsum * ph)
                   + beta * sqrtf(ph) * noise2[idx];
        float p = fmaxf(EPSV, step - c3 * ph);
        sW[idx] = p;
        psum += p;
    }
    float pinv = 1.f / fmaxf(EPSV, psum);
    for (int i = 0; i < K1; i++)
        out[OFF2 + i * K2 + t] = sW[i * K2 + t] * pinv;
}

// ---------------------------------------------------------------------------
// Launcher — static smem only; no attribute calls, no cp.async anywhere
// ---------------------------------------------------------------------------
extern "C" void kernel_launch(void* const* d_in, const int* in_sizes, int n_in,
                              void* d_out, int out_size) {
    const float* x      = (const float*)d_in[0];
    const float* theta0 = (const float*)d_in[1];
    const float* theta1 = (const float*)d_in[2];
    const float* theta2 = (const float*)d_in[3];
    const float* phi0   = (const float*)d_in[4];
    const float* phi1   = (const float*)d_in[5];
    const float* phi2   = (const float*)d_in[6];
    const float* noise0 = (const float*)d_in[7];
    const float* noise1 = (const float*)d_in[8];
    const float* noise2 = (const float*)d_in[9];
    float* out = (float*)d_out;

    // ---- layer 0 ----
    k_transpose<<<dim3((VDIM + 31) / 32, BDIM / 32), dim3(32, 8)>>>(x);
    k_ratio0<<<dim3((VDIM + 127) / 128, BDIM / 128), 256>>>(phi0, theta0);
    k_wszs0<<<dim3((VDIM + 127) / 128, 1), 256>>>(phi0, theta0);
    k_x1part<<<dim3(BDIM / 128, NS0), 256>>>(phi0);
    k_x1red<<<64, 1024>>>(theta0);
    k_colA<<<NCH, K0>>>(phi0, noise0);
    k_colB<<<1, K0>>>();
    k_p0<<<NCH, K0>>>(phi0, noise0, out);
    k_psumfin<<<1, K0>>>();
    k_norm0<<<3750, 1024>>>(out);

    // ---- layer 1 ----
    k_l1denom<<<BDIM / 128, 256>>>(phi1, theta1);
    k_l1dig<<<256, 256>>>();
    k_l1wszs<<<8, 256>>>(theta1);
    k_l1x<<<BDIM / 128, 256>>>(phi1, theta1);
    k_l1tl<<<1, K1>>>(phi1, noise1, out);

    // ---- layer 2 ----
    k_l2denom<<<BDIM / 128, 256>>>(phi2, theta2);
    k_l2dig<<<128, 256>>>();
    k_l2wszs<<<8, 256>>>(theta2);
    k_l2tl<<<1, K2>>>(phi2, noise2, out);
}

// round 8
// speedup vs baseline: 1.2276x; 1.1174x over previous
#include <cuda_runtime.h>
#include <math.h>
#include <stdint.h>

// ---------------------------------------------------------------------------
// Problem constants
// ---------------------------------------------------------------------------
#define EPSV 2.2e-10f
#define VDIM 30000
#define BDIM 512
#define K0 128
#define K1 64
#define K2 32

#define OFF1 (VDIM * K0)            // 3,840,000
#define OFF2 (OFF1 + K0 * K1)       // 3,848,192

#define NS0 120                     // splits for phi0^T @ ratio0 (30000/120 = 250)
#define VCH 250
#define NCH 240                     // row chunks for column reductions (30000/240=125)
#define RCH 125

// ---------------------------------------------------------------------------
// Device scratch (no allocations allowed)
// ---------------------------------------------------------------------------
__device__ float g_xT[VDIM * BDIM];
__device__ float g_ratio0[VDIM * BDIM];
__device__ float g_WSZS0[VDIM * K0];
__device__ float g_x1part[NS0 * K0 * BDIM];
__device__ float g_X1[K0 * BDIM];
__device__ float g_c0part[NCH * 3 * K0];
__device__ float g_c0[4 * K0];
__device__ float g_ppart[NCH * K0];
__device__ float g_pinv0[K0];
__device__ float g_den1[K0 * BDIM];
__device__ float g_ratio1[K0 * BDIM];
__device__ float g_l1wp[8 * K0 * K1];
__device__ float g_X2[K1 * BDIM];
__device__ float g_den2[K1 * BDIM];
__device__ float g_ratio2[K1 * BDIM];
__device__ float g_l2wp[8 * K1 * K2];

// ---------------------------------------------------------------------------
// fp32 digamma (avoid FP64)
// ---------------------------------------------------------------------------
__device__ __forceinline__ float digammaf_(float x) {
    float r = 0.f;
    while (x < 6.f) { r -= 1.f / x; x += 1.f; }
    float inv  = 1.f / x;
    float inv2 = inv * inv;
    float s = logf(x) - 0.5f * inv
        - inv2 * (0.083333333333f
        - inv2 * (0.008333333333f
        - inv2 * (0.003968253968f
        - inv2 * (0.004166666667f
        - inv2 * 0.007575757576f))));
    return r + s;
}

// ---------------------------------------------------------------------------
// 1) transpose x (B,V) -> g_xT (V,B)
// ---------------------------------------------------------------------------
__global__ void k_transpose(const float* __restrict__ x) {
    __shared__ float tile[32][33];
    int v0 = blockIdx.x * 32, b0 = blockIdx.y * 32;
    int tx = threadIdx.x, ty = threadIdx.y;   // (32, 8)
#pragma unroll
    for (int i = 0; i < 32; i += 8) {
        int v = v0 + tx, b = b0 + ty + i;
        tile[ty + i][tx] = (v < VDIM) ? x[(size_t)b * VDIM + v] : 0.f;
    }
    __syncthreads();
#pragma unroll
    for (int i = 0; i < 32; i += 8) {
        int v = v0 + ty + i, b = b0 + tx;
        if (v < VDIM) g_xT[(size_t)v * BDIM + b] = tile[tx][ty + i];
    }
}

// ---------------------------------------------------------------------------
// 2) ratio0 = xT / max(phi0 @ theta0, EPS)
//    block tile 128(v) x 64(b), thread tile 8x4, K=128 (4 steps), reg prefetch
// ---------------------------------------------------------------------------
__global__ void __launch_bounds__(256, 3)
k_ratio0(const float* __restrict__ phi0, const float* __restrict__ theta0) {
    __shared__ float As[32 * 132];   // [k][v] transposed, pitch 132
    __shared__ float Bs[32 * 64];    // [k][b] direct
    int tid = threadIdx.x;
    int v0 = blockIdx.x * 128, b0 = blockIdx.y * 64;
    int tx = tid & 15, ty = tid >> 4;
    int row = ty * 8, col = tx * 4;
    float4 areg[4], breg[2];

    // prologue (k-step 0)
#pragma unroll
    for (int p = 0; p < 4; p++) {          // A: 128x32 = 4 f4/thr
        int slot = tid + p * 256;
        int r = slot >> 3, c4 = (slot & 7) * 4;
        areg[p] = make_float4(0.f, 0.f, 0.f, 0.f);
        if (v0 + r < VDIM)
            areg[p] = *(const float4*)&phi0[(size_t)(v0 + r) * K0 + c4];
    }
#pragma unroll
    for (int p = 0; p < 2; p++) {          // B: 32x64 = 2 f4/thr
        int slot = tid + p * 256;
        int c = slot >> 4, j4 = (slot & 15) * 4;
        breg[p] = *(const float4*)&theta0[(size_t)c * BDIM + b0 + j4];
    }
#pragma unroll
    for (int p = 0; p < 4; p++) {
        int slot = tid + p * 256;
        int r = slot >> 3, c4 = (slot & 7) * 4;
        As[(c4 + 0) * 132 + r] = areg[p].x;
        As[(c4 + 1) * 132 + r] = areg[p].y;
        As[(c4 + 2) * 132 + r] = areg[p].z;
        As[(c4 + 3) * 132 + r] = areg[p].w;
    }
#pragma unroll
    for (int p = 0; p < 2; p++) {
        int slot = tid + p * 256;
        int c = slot >> 4, j4 = (slot & 15) * 4;
        *(float4*)&Bs[c * 64 + j4] = breg[p];
    }
    __syncthreads();

    float acc[8][4] = {};
#pragma unroll 1
    for (int s = 0; s < 4; s++) {
        if (s < 3) {
            int k0 = (s + 1) * 32;
#pragma unroll
            for (int p = 0; p < 4; p++) {
                int slot = tid + p * 256;
                int r = slot >> 3, c4 = (slot & 7) * 4;
                areg[p] = make_float4(0.f, 0.f, 0.f, 0.f);
                if (v0 + r < VDIM)
                    areg[p] = *(const float4*)&phi0[(size_t)(v0 + r) * K0 + k0 + c4];
            }
#pragma unroll
            for (int p = 0; p < 2; p++) {
                int slot = tid + p * 256;
                int c = slot >> 4, j4 = (slot & 15) * 4;
                breg[p] = *(const float4*)&theta0[(size_t)(k0 + c) * BDIM + b0 + j4];
            }
        }
#pragma unroll
        for (int c = 0; c < 32; c++) {
            float4 a0 = *(const float4*)&As[c * 132 + row];
            float4 a1 = *(const float4*)&As[c * 132 + row + 4];
            float4 bv = *(const float4*)&Bs[c * 64 + col];
            float ra[8] = {a0.x, a0.y, a0.z, a0.w, a1.x, a1.y, a1.z, a1.w};
            float rb[4] = {bv.x, bv.y, bv.z, bv.w};
#pragma unroll
            for (int i = 0; i < 8; i++)
#pragma unroll
                for (int j = 0; j < 4; j++) acc[i][j] += ra[i] * rb[j];
        }
        __syncthreads();
        if (s < 3) {
#pragma unroll
            for (int p = 0; p < 4; p++) {
                int slot = tid + p * 256;
                int r = slot >> 3, c4 = (slot & 7) * 4;
                As[(c4 + 0) * 132 + r] = areg[p].x;
                As[(c4 + 1) * 132 + r] = areg[p].y;
                As[(c4 + 2) * 132 + r] = areg[p].z;
                As[(c4 + 3) * 132 + r] = areg[p].w;
            }
#pragma unroll
            for (int p = 0; p < 2; p++) {
                int slot = tid + p * 256;
                int c = slot >> 4, j4 = (slot & 15) * 4;
                *(float4*)&Bs[c * 64 + j4] = breg[p];
            }
            __syncthreads();
        }
    }
#pragma unroll
    for (int i = 0; i < 8; i++) {
        int v = v0 + row + i;
        if (v >= VDIM) break;
        float4 xv = *(const float4*)&g_xT[(size_t)v * BDIM + b0 + col];
        float4 o;
        o.x = xv.x / fmaxf(acc[i][0], EPSV);
        o.y = xv.y / fmaxf(acc[i][1], EPSV);
        o.z = xv.z / fmaxf(acc[i][2], EPSV);
        o.w = xv.w / fmaxf(acc[i][3], EPSV);
        *(float4*)&g_ratio0[(size_t)v * BDIM + b0 + col] = o;
    }
}

// ---------------------------------------------------------------------------
// 3) WSZS0 = phi0 * (ratio0 @ theta0^T)
//    block tile 64(v) x 64(k), thread tile 4x4, contraction b=512 (16 steps)
// ---------------------------------------------------------------------------
__global__ void __launch_bounds__(256, 4)
k_wszs0(const float* __restrict__ phi0, const float* __restrict__ theta0) {
    __shared__ float As[32 * 68];    // [b][v], pitch 68
    __shared__ float Bs[32 * 68];    // [b][k], pitch 68
    int tid = threadIdx.x;
    int v0 = blockIdx.x * 64;
    int kb = blockIdx.y * 64;
    int tx = tid & 15, ty = tid >> 4;
    int row = ty * 4, col = tx * 4;
    float4 areg[2], breg[2];

    // prologue (b-step 0)
#pragma unroll
    for (int p = 0; p < 2; p++) {          // A: ratio0 64v x 32b, transposed store
        int slot = tid + p * 256;
        int r = slot >> 3, c4 = (slot & 7) * 4;
        areg[p] = make_float4(0.f, 0.f, 0.f, 0.f);
        if (v0 + r < VDIM)
            areg[p] = *(const float4*)&g_ratio0[(size_t)(v0 + r) * BDIM + c4];
        // B: theta0^T 32b x 64k <- theta0[k][b], transposed store
        int kk = slot >> 3, b4 = (slot & 7) * 4;
        breg[p] = *(const float4*)&theta0[(size_t)(kb + kk) * BDIM + b4];
    }
#pragma unroll
    for (int p = 0; p < 2; p++) {
        int slot = tid + p * 256;
        int r = slot >> 3, c4 = (slot & 7) * 4;
        As[(c4 + 0) * 68 + r] = areg[p].x; As[(c4 + 1) * 68 + r] = areg[p].y;
        As[(c4 + 2) * 68 + r] = areg[p].z; As[(c4 + 3) * 68 + r] = areg[p].w;
        Bs[(c4 + 0) * 68 + r] = breg[p].x; Bs[(c4 + 1) * 68 + r] = breg[p].y;
        Bs[(c4 + 2) * 68 + r] = breg[p].z; Bs[(c4 + 3) * 68 + r] = breg[p].w;
    }
    __syncthreads();

    float acc[4][4] = {};
#pragma unroll 1
    for (int s = 0; s < 16; s++) {
        if (s < 15) {
            int b0 = (s + 1) * 32;
#pragma unroll
            for (int p = 0; p < 2; p++) {
                int slot = tid + p * 256;
                int r = slot >> 3, c4 = (slot & 7) * 4;
                areg[p] = make_float4(0.f, 0.f, 0.f, 0.f);
                if (v0 + r < VDIM)
                    areg[p] = *(const float4*)&g_ratio0[(size_t)(v0 + r) * BDIM + b0 + c4];
                int kk = slot >> 3, b4 = (slot & 7) * 4;
                breg[p] = *(const float4*)&theta0[(size_t)(kb + kk) * BDIM + b0 + b4];
            }
        }
#pragma unroll
        for (int c = 0; c < 32; c++) {
            float4 a = *(const float4*)&As[c * 68 + row];
            float4 b = *(const float4*)&Bs[c * 68 + col];
            float ra[4] = {a.x, a.y, a.z, a.w};
            float rb[4] = {b.x, b.y, b.z, b.w};
#pragma unroll
            for (int i = 0; i < 4; i++)
#pragma unroll
                for (int j = 0; j < 4; j++) acc[i][j] += ra[i] * rb[j];
        }
        __syncthreads();
        if (s < 15) {
#pragma unroll
            for (int p = 0; p < 2; p++) {
                int slot = tid + p * 256;
                int r = slot >> 3, c4 = (slot & 7) * 4;
                As[(c4 + 0) * 68 + r] = areg[p].x; As[(c4 + 1) * 68 + r] = areg[p].y;
                As[(c4 + 2) * 68 + r] = areg[p].z; As[(c4 + 3) * 68 + r] = areg[p].w;
                Bs[(c4 + 0) * 68 + r] = breg[p].x; Bs[(c4 + 1) * 68 + r] = breg[p].y;
                Bs[(c4 + 2) * 68 + r] = breg[p].z; Bs[(c4 + 3) * 68 + r] = breg[p].w;
            }
            __syncthreads();
        }
    }
#pragma unroll
    for (int i = 0; i < 4; i++) {
        int v = v0 + row + i;
        if (v >= VDIM) break;
        float4 ph = *(const float4*)&phi0[(size_t)v * K0 + kb + col];
        float4 o;
        o.x = ph.x * acc[i][0];
        o.y = ph.y * acc[i][1];
        o.z = ph.z * acc[i][2];
        o.w = ph.w * acc[i][3];
        *(float4*)&g_WSZS0[(size_t)v * K0 + kb + col] = o;
    }
}

// ---------------------------------------------------------------------------
// 4) split-K partials of phi0^T @ ratio0 (deterministic)
//    block tile 128(k) x 64(b), thread tile 8x4, splits NS0=120 (VCH=250)
// ---------------------------------------------------------------------------
__global__ void __launch_bounds__(256, 3)
k_x1part(const float* __restrict__ phi0) {
    __shared__ float As[32 * 128];   // [vv][k]
    __shared__ float Bs[32 * 64];    // [vv][b]
    int tid = threadIdx.x;
    int b0 = blockIdx.x * 64;
    int s_ = blockIdx.y;
    int vbeg = s_ * VCH, vend = vbeg + VCH;
    int tx = tid & 15, ty = tid >> 4;
    int row = ty * 8, col = tx * 4;
    const int nsteps = (VCH + 31) / 32;   // 8
    float4 areg[4], breg[2];

#pragma unroll
    for (int p = 0; p < 4; p++) {          // A: phi0 32v x 128k direct
        int slot = tid + p * 256;
        int vv = slot >> 5, j4 = (slot & 31) * 4;
        int vg = vbeg + vv;
        areg[p] = make_float4(0.f, 0.f, 0.f, 0.f);
        if (vg < vend)
            areg[p] = *(const float4*)&phi0[(size_t)vg * K0 + j4];
    }
#pragma unroll
    for (int p = 0; p < 2; p++) {          // B: ratio0 32v x 64b direct
        int slot = tid + p * 256;
        int vv = slot >> 4, j4 = (slot & 15) * 4;
        int vg = vbeg + vv;
        breg[p] = make_float4(0.f, 0.f, 0.f, 0.f);
        if (vg < vend)
            breg[p] = *(const float4*)&g_ratio0[(size_t)vg * BDIM + b0 + j4];
    }
#pragma unroll
    for (int p = 0; p < 4; p++) {
        int slot = tid + p * 256;
        int vv = slot >> 5, j4 = (slot & 31) * 4;
        *(float4*)&As[vv * 128 + j4] = areg[p];
    }
#pragma unroll
    for (int p = 0; p < 2; p++) {
        int slot = tid + p * 256;
        int vv = slot >> 4, j4 = (slot & 15) * 4;
        *(float4*)&Bs[vv * 64 + j4] = breg[p];
    }
    __syncthreads();

    float acc[8][4] = {};
#pragma unroll 1
    for (int s = 0; s < nsteps; s++) {
        if (s + 1 < nsteps) {
            int v0 = vbeg + (s + 1) * 32;
#pragma unroll
            for (int p = 0; p < 4; p++) {
                int slot = tid + p * 256;
                int vv = slot >> 5, j4 = (slot & 31) * 4;
                int vg = v0 + vv;
                areg[p] = make_float4(0.f, 0.f, 0.f, 0.f);
                if (vg < vend)
                    areg[p] = *(const float4*)&phi0[(size_t)vg * K0 + j4];
            }
#pragma unroll
            for (int p = 0; p < 2; p++) {
                int slot = tid + p * 256;
                int vv = slot >> 4, j4 = (slot & 15) * 4;
                int vg = v0 + vv;
                breg[p] = make_float4(0.f, 0.f, 0.f, 0.f);
                if (vg < vend)
                    breg[p] = *(const float4*)&g_ratio0[(size_t)vg * BDIM + b0 + j4];
            }
        }
#pragma unroll
        for (int c = 0; c < 32; c++) {
            float4 a0 = *(const float4*)&As[c * 128 + row];
            float4 a1 = *(const float4*)&As[c * 128 + row + 4];
            float4 bv = *(const float4*)&Bs[c * 64 + col];
            float ra[8] = {a0.x, a0.y, a0.z, a0.w, a1.x, a1.y, a1.z, a1.w};
            float rb[4] = {bv.x, bv.y, bv.z, bv.w};
#pragma unroll
            for (int i = 0; i < 8; i++)
#pragma unroll
                for (int j = 0; j < 4; j++) acc[i][j] += ra[i] * rb[j];
        }
        __syncthreads();
        if (s + 1 < nsteps) {
#pragma unroll
            for (int p = 0; p < 4; p++) {
                int slot = tid + p * 256;
                int vv = slot >> 5, j4 = (slot & 31) * 4;
                *(float4*)&As[vv * 128 + j4] = areg[p];
            }
#pragma unroll
            for (int p = 0; p < 2; p++) {
                int slot = tid + p * 256;
                int vv = slot >> 4, j4 = (slot & 15) * 4;
                *(float4*)&Bs[vv * 64 + j4] = breg[p];
            }
            __syncthreads();
        }
    }
    float* dst = &g_x1part[(size_t)s_ * K0 * BDIM];
#pragma unroll
    for (int i = 0; i < 8; i++)
        *(float4*)&dst[(size_t)(row + i) * BDIM + b0 + col] =
            make_float4(acc[i][0], acc[i][1], acc[i][2], acc[i][3]);
}

// 5) reduce partials, multiply by theta0 -> X1
__global__ void k_x1red(const float* __restrict__ theta0) {
    int idx = blockIdx.x * 1024 + threadIdx.x;
    float s = 0.f;
#pragma unroll 10
    for (int p = 0; p < NS0; p++) s += g_x1part[(size_t)p * K0 * BDIM + idx];
    g_X1[idx] = theta0[idx] * s;
}

// ---------------------------------------------------------------------------
// 6/7) column stats for layer-0 TLASGR
// ---------------------------------------------------------------------------
__global__ void k_colA(const float* __restrict__ phi0,
                       const float* __restrict__ noise0) {
    int t = threadIdx.x;
    int ch = blockIdx.x;
    float sw = 0.f, sp = 0.f, sn = 0.f;
    int vbeg = ch * RCH;
#pragma unroll 5
    for (int r = 0; r < RCH; r++) {
        size_t idx = (size_t)(vbeg + r) * K0 + t;
        sw += g_WSZS0[idx];
        float ph = phi0[idx];
        sp += ph;
        sn += sqrtf(ph) * noise0[idx];
    }
    g_c0part[ch * 384 + t]        = sw;
    g_c0part[ch * 384 + 128 + t]  = sp;
    g_c0part[ch * 384 + 256 + t]  = sn;
}

__global__ void k_colB() {
    int t = threadIdx.x;
    float sw = 0.f, sp = 0.f, sn = 0.f;
#pragma unroll 10
    for (int ch = 0; ch < NCH; ch++) {
        sw += g_c0part[ch * 384 + t];
        sp += g_c0part[ch * 384 + 128 + t];
        sn += g_c0part[ch * 384 + 256 + t];
    }
    float NDot   = 100.f * sw;
    float tmpsum = NDot + 0.1f * (float)VDIM;
    float inv_n  = 1.f / fmaxf(NDot, EPSV);
    float beta   = sqrtf(2.f * inv_n);
    float ssum   = sp + inv_n * (tmpsum - tmpsum * sp) + beta * sn;
    g_c0[t]           = inv_n;
    g_c0[128 + t]     = beta;
    g_c0[256 + t]     = tmpsum;
    g_c0[384 + t]     = ssum - 1.f;
}

// 8) p = max(EPS, step - (ssum-1)*phi); write + per-chunk psum
__global__ void k_p0(const float* __restrict__ phi0,
                     const float* __restrict__ noise0,
                     float* __restrict__ out) {
    int t = threadIdx.x;
    int ch = blockIdx.x;
    float inv_n = g_c0[t], beta = g_c0[128 + t];
    float tmpsum = g_c0[256 + t], c3 = g_c0[384 + t];
    float psum = 0.f;
    int vbeg = ch * RCH;
#pragma unroll 5
    for (int r = 0; r < RCH; r++) {
        size_t idx = (size_t)(vbeg + r) * K0 + t;
        float ph  = phi0[idx];
        float tmp = 100.f * g_WSZS0[idx] + 0.1f;
        float step = ph + inv_n * (tmp - tmpsum * ph)
                   + beta * sqrtf(ph) * noise0[idx];
        float p = fmaxf(EPSV, step - c3 * ph);
        out[idx] = p;
        psum += p;
    }
    g_ppart[ch * K0 + t] = psum;
}

__global__ void k_psumfin() {
    int t = threadIdx.x;
    float s = 0.f;
#pragma unroll 10
    for (int ch = 0; ch < NCH; ch++) s += g_ppart[ch * K0 + t];
    g_pinv0[t] = 1.f / fmaxf(EPSV, s);
}

__global__ void k_norm0(float* __restrict__ out) {
    int idx = blockIdx.x * 1024 + threadIdx.x;
    out[idx] *= g_pinv0[idx & 127];
}

// ---------------------------------------------------------------------------
// Layer 1: denom = phi1@theta1 (128x512, K=64), then elementwise digamma
// ---------------------------------------------------------------------------
__global__ void __launch_bounds__(256)
k_l1denom(const float* __restrict__ phi1, const float* __restrict__ theta1) {
    __shared__ float As[32][132];
    __shared__ float Bs[32][128];
    int tid = threadIdx.x;
    int b0 = blockIdx.x * 128;
    int tx = tid & 15, ty = tid >> 4;
    int row = ty * 8, col = tx * 8;
    float acc[8][8] = {};
    for (int k0 = 0; k0 < K1; k0 += 32) {
#pragma unroll
        for (int p = 0; p < 4; p++) {
            int slot = tid + p * 256;
            int r = slot >> 3, c4 = (slot & 7) * 4;
            float4 a = *(const float4*)&phi1[(size_t)r * K1 + k0 + c4];
            As[c4 + 0][r] = a.x; As[c4 + 1][r] = a.y;
            As[c4 + 2][r] = a.z; As[c4 + 3][r] = a.w;
        }
#pragma unroll
        for (int p = 0; p < 4; p++) {
            int slot = tid + p * 256;
            int c = slot >> 5, j4 = (slot & 31) * 4;
            *(float4*)&Bs[c][j4] =
                *(const float4*)&theta1[(size_t)(k0 + c) * BDIM + b0 + j4];
        }
        __syncthreads();
#pragma unroll
        for (int c = 0; c < 32; c++) {
            float4 a0 = *(const float4*)&As[c][row];
            float4 a1 = *(const float4*)&As[c][row + 4];
            float4 bv0 = *(const float4*)&Bs[c][col];
            float4 bv1 = *(const float4*)&Bs[c][col + 4];
            float ra[8] = {a0.x, a0.y, a0.z, a0.w, a1.x, a1.y, a1.z, a1.w};
            float rb[8] = {bv0.x, bv0.y, bv0.z, bv0.w, bv1.x, bv1.y, bv1.z, bv1.w};
#pragma unroll
            for (int i = 0; i < 8; i++)
#pragma unroll
                for (int j = 0; j < 8; j++) acc[i][j] += ra[i] * rb[j];
        }
        __syncthreads();
    }
#pragma unroll
    for (int i = 0; i < 8; i++)
#pragma unroll
        for (int j = 0; j < 8; j++)
            g_den1[(size_t)(row + i) * BDIM + b0 + col + j] = acc[i][j];
}

__global__ void k_l1dig() {
    int idx = blockIdx.x * 256 + threadIdx.x;   // 256 blocks -> 65536
    float d = fmaxf(g_den1[idx], EPSV);
    g_ratio1[idx] = digammaf_(d + g_X1[idx]) - digammaf_(d);
}

// Layer 1 WSZS partials: (128 x 64) = ratio1 @ theta1^T, split over b (8x64)
__global__ void k_l1wszs(const float* __restrict__ theta1) {
    __shared__ float As[32][132];
    __shared__ float Bs[32][68];
    int tid = threadIdx.x;
    int s = blockIdx.x;
    int bbase = s * 64;
    int tx = tid & 15, ty = tid >> 4;
    int row = ty * 8, col = tx * 4;
    float acc[8][4] = {};
    for (int bc = 0; bc < 64; bc += 32) {
        int b0 = bbase + bc;
#pragma unroll
        for (int p = 0; p < 4; p++) {
            int slot = tid + p * 256;
            int r = slot >> 3, c4 = (slot & 7) * 4;
            float4 a = *(const float4*)&g_ratio1[(size_t)r * BDIM + b0 + c4];
            As[c4 + 0][r] = a.x; As[c4 + 1][r] = a.y;
            As[c4 + 2][r] = a.z; As[c4 + 3][r] = a.w;
        }
#pragma unroll
        for (int p = 0; p < 2; p++) {
            int slot = tid + p * 256;
            int j = slot >> 3, c4 = (slot & 7) * 4;
            float4 t = *(const float4*)&theta1[(size_t)j * BDIM + b0 + c4];
            Bs[c4 + 0][j] = t.x; Bs[c4 + 1][j] = t.y;
            Bs[c4 + 2][j] = t.z; Bs[c4 + 3][j] = t.w;
        }
        __syncthreads();
#pragma unroll
        for (int c = 0; c < 32; c++) {
            float ra[8], rb[4];
#pragma unroll
            for (int i = 0; i < 8; i++) ra[i] = As[c][row + i];
#pragma unroll
            for (int j = 0; j < 4; j++) rb[j] = Bs[c][col + j];
#pragma unroll
            for (int i = 0; i < 8; i++)
#pragma unroll
                for (int j = 0; j < 4; j++) acc[i][j] += ra[i] * rb[j];
        }
        __syncthreads();
    }
    float* dst = &g_l1wp[(size_t)s * K0 * K1];
#pragma unroll
    for (int i = 0; i < 8; i++)
#pragma unroll
        for (int j = 0; j < 4; j++)
            dst[(size_t)(row + i) * K1 + col + j] = acc[i][j];
}

// Layer 1 counts: X2 = theta1 * (phi1^T @ ratio1), out (64, B), K=128
__global__ void k_l1x(const float* __restrict__ phi1,
                      const float* __restrict__ theta1) {
    __shared__ float As[32][64];
    __shared__ float Bs[32][128];
    int tid = threadIdx.x;
    int b0 = blockIdx.x * 128;
    int tx = tid & 15, ty = tid >> 4;
    int row = ty * 4, col = tx * 8;
    float acc[4][8] = {};
    for (int i0 = 0; i0 < K0; i0 += 32) {
#pragma unroll
        for (int p = 0; p < 2; p++) {
            int slot = tid + p * 256;
            int ii = slot >> 4, j4 = (slot & 15) * 4;
            *(float4*)&As[ii][j4] =
                *(const float4*)&phi1[(size_t)(i0 + ii) * K1 + j4];
        }
#pragma unroll
        for (int p = 0; p < 4; p++) {
            int slot = tid + p * 256;
            int ii = slot >> 5, j4 = (slot & 31) * 4;
            *(float4*)&Bs[ii][j4] =
                *(const float4*)&g_ratio1[(size_t)(i0 + ii) * BDIM + b0 + j4];
        }
        __syncthreads();
#pragma unroll
        for (int c = 0; c < 32; c++) {
            float ra[4], rb[8];
#pragma unroll
            for (int i = 0; i < 4; i++) ra[i] = As[c][row + i];
#pragma unroll
            for (int j = 0; j < 8; j++) rb[j] = Bs[c][col + j];
#pragma unroll
            for (int i = 0; i < 4; i++)
#pragma unroll
                for (int j = 0; j < 8; j++) acc[i][j] += ra[i] * rb[j];
        }
        __syncthreads();
    }
#pragma unroll
    for (int i = 0; i < 4; i++)
#pragma unroll
        for (int j = 0; j < 8; j++) {
            size_t idx = (size_t)(row + i) * BDIM + b0 + col + j;
            g_X2[idx] = theta1[idx] * acc[i][j];
        }
}

// Layer 1 TLASGR + simplex projection (one CTA, thread-per-column)
__global__ void k_l1tl(const float* __restrict__ phi1,
                       const float* __restrict__ noise1,
                       float* __restrict__ out) {
    __shared__ float sW[K0 * K1];
    int t = threadIdx.x;
    float sw = 0.f, sp = 0.f, sn = 0.f;
    for (int i = 0; i < K0; i++) {
        int idx = i * K1 + t;
        float w = 0.f;
#pragma unroll
        for (int s = 0; s < 8; s++) w += g_l1wp[s * K0 * K1 + idx];
        float ph = phi1[idx];
        w *= ph;
        sW[idx] = w;
        sw += w; sp += ph; sn += sqrtf(ph) * noise1[idx];
    }
    float NDot   = 100.f * sw;
    float tmpsum = NDot + 0.1f * (float)K0;
    float inv_n  = 1.f / fmaxf(NDot, EPSV);
    float beta   = sqrtf(2.f * inv_n);
    float ssum   = sp + inv_n * (tmpsum - tmpsum * sp) + beta * sn;
    float c3     = ssum - 1.f;
    float psum = 0.f;
    for (int i = 0; i < K0; i++) {
        int idx = i * K1 + t;
        float ph  = phi1[idx];
        float tmp = 100.f * sW[idx] + 0.1f;
        float step = ph + inv_n * (tmp - tmpsum * ph)
                   + beta * sqrtf(ph) * noise1[idx];
        float p = fmaxf(EPSV, step - c3 * ph);
        sW[idx] = p;
        psum += p;
    }
    float pinv = 1.f / fmaxf(EPSV, psum);
    for (int i = 0; i < K0; i++)
        out[OFF1 + i * K1 + t] = sW[i * K1 + t] * pinv;
}

// ---------------------------------------------------------------------------
// Layer 2: denom (64,B) K=32, then digamma
// ---------------------------------------------------------------------------
__global__ void k_l2denom(const float* __restrict__ phi2,
                          const float* __restrict__ theta2) {
    __shared__ float As[32][68];
    __shared__ float Bs[32][128];
    int tid = threadIdx.x;
    int b0 = blockIdx.x * 128;
    int tx = tid & 15, ty = tid >> 4;
    int row = ty * 4, col = tx * 8;
    float acc[4][8] = {};
    {
#pragma unroll
        for (int p = 0; p < 2; p++) {
            int slot = tid + p * 256;
            int r = slot >> 3, c4 = (slot & 7) * 4;
            float4 a = *(const float4*)&phi2[(size_t)r * K2 + c4];
            As[c4 + 0][r] = a.x; As[c4 + 1][r] = a.y;
            As[c4 + 2][r] = a.z; As[c4 + 3][r] = a.w;
        }
#pragma unroll
        for (int p = 0; p < 4; p++) {
            int slot = tid + p * 256;
            int c = slot >> 5, j4 = (slot & 31) * 4;
            *(float4*)&Bs[c][j4] =
                *(const float4*)&theta2[(size_t)c * BDIM + b0 + j4];
        }
        __syncthreads();
#pragma unroll
        for (int c = 0; c < 32; c++) {
            float ra[4], rb[8];
#pragma unroll
            for (int i = 0; i < 4; i++) ra[i] = As[c][row + i];
#pragma unroll
            for (int j = 0; j < 8; j++) rb[j] = Bs[c][col + j];
#pragma unroll
            for (int i = 0; i < 4; i++)
#pragma unroll
                for (int j = 0; j < 8; j++) acc[i][j] += ra[i] * rb[j];
        }
    }
#pragma unroll
    for (int i = 0; i < 4; i++)
#pragma unroll
        for (int j = 0; j < 8; j++)
            g_den2[(size_t)(row + i) * BDIM + b0 + col + j] = acc[i][j];
}

__global__ void k_l2dig() {
    int idx = blockIdx.x * 256 + threadIdx.x;   // 128 blocks -> 32768
    float d = fmaxf(g_den2[idx], EPSV);
    g_ratio2[idx] = digammaf_(d + g_X2[idx]) - digammaf_(d);
}

// Layer 2 WSZS partials: (64 x 32) = ratio2 @ theta2^T, split over b (8x64)
__global__ void k_l2wszs(const float* __restrict__ theta2) {
    __shared__ float As[32][68];
    __shared__ float Bs[32][36];
    int tid = threadIdx.x;
    int s = blockIdx.x;
    int bbase = s * 64;
    int tx = tid & 15, ty = tid >> 4;
    int row = ty * 4, col = tx * 2;
    float acc[4][2] = {};
    for (int bc = 0; bc < 64; bc += 32) {
        int b0 = bbase + bc;
#pragma unroll
        for (int p = 0; p < 2; p++) {
            int slot = tid + p * 256;
            int r = slot >> 3, c4 = (slot & 7) * 4;
            float4 a = *(const float4*)&g_ratio2[(size_t)r * BDIM + b0 + c4];
            As[c4 + 0][r] = a.x; As[c4 + 1][r] = a.y;
            As[c4 + 2][r] = a.z; As[c4 + 3][r] = a.w;
        }
        {
            int slot = tid;
            int j = slot >> 3, c4 = (slot & 7) * 4;
            float4 t = *(const float4*)&theta2[(size_t)j * BDIM + b0 + c4];
            Bs[c4 + 0][j] = t.x; Bs[c4 + 1][j] = t.y;
            Bs[c4 + 2][j] = t.z; Bs[c4 + 3][j] = t.w;
        }
        __syncthreads();
#pragma unroll
        for (int c = 0; c < 32; c++) {
            float ra[4], rb[2];
#pragma unroll
            for (int i = 0; i < 4; i++) ra[i] = As[c][row + i];
#pragma unroll
            for (int j = 0; j < 2; j++) rb[j] = Bs[c][col + j];
#pragma unroll
            for (int i = 0; i < 4; i++)
#pragma unroll
                for (int j = 0; j < 2; j++) acc[i][j] += ra[i] * rb[j];
        }
        __syncthreads();
    }
    float* dst = &g_l2wp[(size_t)s * K1 * K2];
#pragma unroll
    for (int i = 0; i < 4; i++)
#pragma unroll
        for (int j = 0; j < 2; j++)
            dst[(size_t)(row + i) * K2 + col + j] = acc[i][j];
}

// Layer 2 TLASGR (one CTA, 32 columns)
__global__ void k_l2tl(const float* __restrict__ phi2,
                       const float* __restrict__ noise2,
                       float* __restrict__ out) {
    __shared__ float sW[K1 * K2];
    int t = threadIdx.x;
    float sw = 0.f, sp = 0.f, sn = 0.f;
    for (int i = 0; i < K1; i++) {
        int idx = i * K2 + t;
        float w = 0.f;
#pragma unroll
        for (int s = 0; s < 8; s++) w += g_l2wp[s * K1 * K2 + idx];
        float ph = phi2[idx];
        w *= ph;
        sW[idx] = w;
        sw += w; sp += ph; sn += sqrtf(ph) * noise2[idx];
    }
    float NDot   = 100.f * sw;
    float tmpsum = NDot + 0.1f * (float)K1;
    float inv_n  = 1.f / fmaxf(NDot, EPSV);
    float beta   = sqrtf(2.f * inv_n);
    float ssum   = sp + inv_n * (tmpsum - tmpsum * sp) + beta * sn;
    float c3     = ssum - 1.f;
    float psum = 0.f;
    for (int i = 0; i < K1; i++) {
        int idx = i * K2 + t;
        float ph  = phi2[idx];
        float tmp = 100.f * sW[idx] + 0.1f;
        float step = ph + inv_n * (tmp - tmpsum * ph)
                   + beta * sqrtf(ph) * noise2[idx];
        float p = fmaxf(EPSV, step - c3 * ph);
        sW[idx] = p;
        psum += p;
    }
    float pinv = 1.f / fmaxf(EPSV, psum);
    for (int i = 0; i < K1; i++)
        out[OFF2 + i * K2 + t] = sW[i * K2 + t] * pinv;
}

// ---------------------------------------------------------------------------
// Launcher — static smem only; no attribute calls, no cp.async anywhere
// ---------------------------------------------------------------------------
extern "C" void kernel_launch(void* const* d_in, const int* in_sizes, int n_in,
                              void* d_out, int out_size) {
    const float* x      = (const float*)d_in[0];
    const float* theta0 = (const float*)d_in[1];
    const float* theta1 = (const float*)d_in[2];
    const float* theta2 = (const float*)d_in[3];
    const float* phi0   = (const float*)d_in[4];
    const float* phi1   = (const float*)d_in[5];
    const float* phi2   = (const float*)d_in[6];
    const float* noise0 = (const float*)d_in[7];
    const float* noise1 = (const float*)d_in[8];
    const float* noise2 = (const float*)d_in[9];
    float* out = (float*)d_out;

    // ---- layer 0 ----
    k_transpose<<<dim3((VDIM + 31) / 32, BDIM / 32), dim3(32, 8)>>>(x);
    k_ratio0<<<dim3((VDIM + 127) / 128, BDIM / 64), 256>>>(phi0, theta0);
    k_wszs0<<<dim3((VDIM + 63) / 64, K0 / 64), 256>>>(phi0, theta0);
    k_x1part<<<dim3(BDIM / 64, NS0), 256>>>(phi0);
    k_x1red<<<64, 1024>>>(theta0);
    k_colA<<<NCH, K0>>>(phi0, noise0);
    k_colB<<<1, K0>>>();
    k_p0<<<NCH, K0>>>(phi0, noise0, out);
    k_psumfin<<<1, K0>>>();
    k_norm0<<<3750, 1024>>>(out);

    // ---- layer 1 ----
    k_l1denom<<<BDIM / 128, 256>>>(phi1, theta1);
    k_l1dig<<<256, 256>>>();
    k_l1wszs<<<8, 256>>>(theta1);
    k_l1x<<<BDIM / 128, 256>>>(phi1, theta1);
    k_l1tl<<<1, K1>>>(phi1, noise1, out);

    // ---- layer 2 ----
    k_l2denom<<<BDIM / 128, 256>>>(phi2, theta2);
    k_l2dig<<<128, 256>>>();
    k_l2wszs<<<8, 256>>>(theta2);
    k_l2tl<<<1, K2>>>(phi2, noise2, out);
}

// round 10
// speedup vs baseline: 1.5380x; 1.2529x over previous
#include <cuda_runtime.h>
#include <math.h>
#include <stdint.h>

// ---------------------------------------------------------------------------
// Problem constants
// ---------------------------------------------------------------------------
#define EPSV 2.2e-10f
#define VDIM 30000
#define BDIM 512
#define K0 128
#define K1 64
#define K2 32

#define OFF1 (VDIM * K0)            // 3,840,000
#define OFF2 (OFF1 + K0 * K1)       // 3,848,192

#define NS0 120                     // splits for phi0^T @ ratio0 (30000/120 = 250)
#define VCH 250
#define NCH 240                     // row chunks for column reductions (30000/240=125)
#define RCH 125

// ---------------------------------------------------------------------------
// Device scratch (no allocations allowed)
// ---------------------------------------------------------------------------
__device__ float g_xT[VDIM * BDIM];
__device__ float g_ratio0[VDIM * BDIM];
__device__ float g_WSZS0[VDIM * K0];
__device__ float g_x1part[NS0 * K0 * BDIM];
__device__ float g_X1[K0 * BDIM];
__device__ float g_c0part[NCH * 3 * K0];
__device__ float g_c0[4 * K0];
__device__ float g_ppart[NCH * K0];
__device__ float g_pinv0[K0];
__device__ float g_den1[K0 * BDIM];
__device__ float g_ratio1[K0 * BDIM];
__device__ float g_l1wp[8 * K0 * K1];
__device__ float g_X2[K1 * BDIM];
__device__ float g_den2[K1 * BDIM];
__device__ float g_ratio2[K1 * BDIM];
__device__ float g_l2wp[8 * K1 * K2];

// ---------------------------------------------------------------------------
// tf32 helpers (warp-level mma.sync; fp32 accumulate)
// ---------------------------------------------------------------------------
__device__ __forceinline__ float tf32c(float x) {
    uint32_t u;
    asm("cvt.rna.tf32.f32 %0, %1;" : "=r"(u) : "f"(x));
    return __uint_as_float(u);
}
__device__ __forceinline__ float4 tf32c4(float4 v) {
    return make_float4(tf32c(v.x), tf32c(v.y), tf32c(v.z), tf32c(v.w));
}
// D += A(16x8,row) * B(8x8,col); a0..a3/b0..b1 hold tf32 bit patterns
__device__ __forceinline__ void mma_tf32(float* d,
                                         float a0, float a1, float a2, float a3,
                                         float b0, float b1) {
    uint32_t A0 = __float_as_uint(a0), A1 = __float_as_uint(a1);
    uint32_t A2 = __float_as_uint(a2), A3 = __float_as_uint(a3);
    uint32_t B0 = __float_as_uint(b0), B1 = __float_as_uint(b1);
    asm volatile(
        "mma.sync.aligned.m16n8k8.row.col.f32.tf32.tf32.f32 "
        "{%0,%1,%2,%3}, {%4,%5,%6,%7}, {%8,%9}, {%0,%1,%2,%3};"
        : "+f"(d[0]), "+f"(d[1]), "+f"(d[2]), "+f"(d[3])
        : "r"(A0), "r"(A1), "r"(A2), "r"(A3), "r"(B0), "r"(B1));
}

// ---------------------------------------------------------------------------
// fp32 digamma (avoid FP64)
// ---------------------------------------------------------------------------
__device__ __forceinline__ float digammaf_(float x) {
    float r = 0.f;
    while (x < 6.f) { r -= 1.f / x; x += 1.f; }
    float inv  = 1.f / x;
    float inv2 = inv * inv;
    float s = logf(x) - 0.5f * inv
        - inv2 * (0.083333333333f
        - inv2 * (0.008333333333f
        - inv2 * (0.003968253968f
        - inv2 * (0.004166666667f
        - inv2 * 0.007575757576f))));
    return r + s;
}

// ---------------------------------------------------------------------------
// 1) transpose x (B,V) -> g_xT (V,B)
// ---------------------------------------------------------------------------
__global__ void k_transpose(const float* __restrict__ x) {
    __shared__ float tile[32][33];
    int v0 = blockIdx.x * 32, b0 = blockIdx.y * 32;
    int tx = threadIdx.x, ty = threadIdx.y;   // (32, 8)
#pragma unroll
    for (int i = 0; i < 32; i += 8) {
        int v = v0 + tx, b = b0 + ty + i;
        tile[ty + i][tx] = (v < VDIM) ? x[(size_t)b * VDIM + v] : 0.f;
    }
    __syncthreads();
#pragma unroll
    for (int i = 0; i < 32; i += 8) {
        int v = v0 + ty + i, b = b0 + tx;
        if (v < VDIM) g_xT[(size_t)v * BDIM + b] = tile[tx][ty + i];
    }
}

// ---------------------------------------------------------------------------
// 2) ratio0 = xT / max(phi0 @ theta0, EPS)   tensor-core tf32
//    CTA 128(v) x 64(b); 8 warps of 32x32; K=128 (4 chunks of 32)
// ---------------------------------------------------------------------------
__global__ void __launch_bounds__(256)
k_ratio0(const float* __restrict__ phi0, const float* __restrict__ theta0) {
    __shared__ float As[128 * 36];   // [v][k-chunk] row-major, pitch 36
    __shared__ float Bs[32 * 68];    // [k-chunk][b], pitch 68
    int tid = threadIdx.x;
    int v0 = blockIdx.x * 128, b0 = blockIdx.y * 64;
    int lane = tid & 31, wid = tid >> 5;
    int grp = lane >> 2, q = lane & 3;
    int m0w = (wid >> 1) * 32, n0w = (wid & 1) * 32;
    float4 areg[4], breg[2];

    // prologue: chunk 0
#pragma unroll
    for (int p = 0; p < 4; p++) {
        int slot = tid + p * 256;
        int r = slot >> 3, c4 = (slot & 7) * 4;
        areg[p] = make_float4(0.f, 0.f, 0.f, 0.f);
        if (v0 + r < VDIM)
            areg[p] = *(const float4*)&phi0[(size_t)(v0 + r) * K0 + c4];
    }
#pragma unroll
    for (int p = 0; p < 2; p++) {
        int slot = tid + p * 256;
        int c = slot >> 4, j4 = (slot & 15) * 4;
        breg[p] = *(const float4*)&theta0[(size_t)c * BDIM + b0 + j4];
    }
#pragma unroll
    for (int p = 0; p < 4; p++) {
        int slot = tid + p * 256;
        int r = slot >> 3, c4 = (slot & 7) * 4;
        *(float4*)&As[r * 36 + c4] = tf32c4(areg[p]);
    }
#pragma unroll
    for (int p = 0; p < 2; p++) {
        int slot = tid + p * 256;
        int c = slot >> 4, j4 = (slot & 15) * 4;
        *(float4*)&Bs[c * 68 + j4] = tf32c4(breg[p]);
    }
    __syncthreads();

    float acc[2][4][4] = {};
#pragma unroll 1
    for (int ch = 0; ch < 4; ch++) {
        if (ch < 3) {
            int kc = (ch + 1) * 32;
#pragma unroll
            for (int p = 0; p < 4; p++) {
                int slot = tid + p * 256;
                int r = slot >> 3, c4 = (slot & 7) * 4;
                areg[p] = make_float4(0.f, 0.f, 0.f, 0.f);
                if (v0 + r < VDIM)
                    areg[p] = *(const float4*)&phi0[(size_t)(v0 + r) * K0 + kc + c4];
            }
#pragma unroll
            for (int p = 0; p < 2; p++) {
                int slot = tid + p * 256;
                int c = slot >> 4, j4 = (slot & 15) * 4;
                breg[p] = *(const float4*)&theta0[(size_t)(kc + c) * BDIM + b0 + j4];
            }
        }
#pragma unroll
        for (int kk = 0; kk < 32; kk += 8) {
            float a[2][4], b[4][2];
#pragma unroll
            for (int ms = 0; ms < 2; ms++) {
                int base = (m0w + ms * 16 + grp) * 36 + kk + q;
                a[ms][0] = As[base];
                a[ms][1] = As[base + 8 * 36];
                a[ms][2] = As[base + 4];
                a[ms][3] = As[base + 8 * 36 + 4];
            }
#pragma unroll
            for (int ns = 0; ns < 4; ns++) {
                int cb = n0w + ns * 8 + grp;
                b[ns][0] = Bs[(kk + q) * 68 + cb];
                b[ns][1] = Bs[(kk + q + 4) * 68 + cb];
            }
#pragma unroll
            for (int ms = 0; ms < 2; ms++)
#pragma unroll
                for (int ns = 0; ns < 4; ns++)
                    mma_tf32(acc[ms][ns], a[ms][0], a[ms][1], a[ms][2], a[ms][3],
                             b[ns][0], b[ns][1]);
        }
        __syncthreads();
        if (ch < 3) {
#pragma unroll
            for (int p = 0; p < 4; p++) {
                int slot = tid + p * 256;
                int r = slot >> 3, c4 = (slot & 7) * 4;
                *(float4*)&As[r * 36 + c4] = tf32c4(areg[p]);
            }
#pragma unroll
            for (int p = 0; p < 2; p++) {
                int slot = tid + p * 256;
                int c = slot >> 4, j4 = (slot & 15) * 4;
                *(float4*)&Bs[c * 68 + j4] = tf32c4(breg[p]);
            }
            __syncthreads();
        }
    }
    // epilogue: d0,d1 -> (grp, 2q..2q+1); d2,d3 -> (grp+8, ...)
#pragma unroll
    for (int ms = 0; ms < 2; ms++) {
        int m = v0 + m0w + ms * 16 + grp;
#pragma unroll
        for (int ns = 0; ns < 4; ns++) {
            int c = b0 + n0w + ns * 8 + 2 * q;
            if (m < VDIM) {
                float2 xv = *(const float2*)&g_xT[(size_t)m * BDIM + c];
                float2 o = {xv.x / fmaxf(acc[ms][ns][0], EPSV),
                            xv.y / fmaxf(acc[ms][ns][1], EPSV)};
                *(float2*)&g_ratio0[(size_t)m * BDIM + c] = o;
            }
            if (m + 8 < VDIM) {
                float2 xv = *(const float2*)&g_xT[(size_t)(m + 8) * BDIM + c];
                float2 o = {xv.x / fmaxf(acc[ms][ns][2], EPSV),
                            xv.y / fmaxf(acc[ms][ns][3], EPSV)};
                *(float2*)&g_ratio0[(size_t)(m + 8) * BDIM + c] = o;
            }
        }
    }
}

// ---------------------------------------------------------------------------
// 3) WSZS0 = phi0 * (ratio0 @ theta0^T)   tensor-core tf32
//    CTA 64(v) x 128(k); 8 warps (2m x 4n) of 32x32; contraction b (16 chunks)
// ---------------------------------------------------------------------------
__global__ void __launch_bounds__(256)
k_wszs0(const float* __restrict__ phi0, const float* __restrict__ theta0) {
    __shared__ float As[64 * 36];    // [v][b-chunk], pitch 36
    __shared__ float Bs[32 * 132];   // [b-chunk][k], pitch 132
    int tid = threadIdx.x;
    int v0 = blockIdx.x * 64;
    int lane = tid & 31, wid = tid >> 5;
    int grp = lane >> 2, q = lane & 3;
    int m0w = (wid >> 2) * 32, n0w = (wid & 3) * 32;
    float4 areg[2], breg[4];

    // prologue: chunk 0 (bc = 0)
#pragma unroll
    for (int p = 0; p < 2; p++) {
        int slot = tid + p * 256;
        int r = slot >> 3, c4 = (slot & 7) * 4;
        areg[p] = make_float4(0.f, 0.f, 0.f, 0.f);
        if (v0 + r < VDIM)
            areg[p] = *(const float4*)&g_ratio0[(size_t)(v0 + r) * BDIM + c4];
    }
#pragma unroll
    for (int p = 0; p < 4; p++) {
        int slot = tid + p * 256;
        int k = slot >> 3, b4 = (slot & 7) * 4;
        breg[p] = *(const float4*)&theta0[(size_t)k * BDIM + b4];
    }
#pragma unroll
    for (int p = 0; p < 2; p++) {
        int slot = tid + p * 256;
        int r = slot >> 3, c4 = (slot & 7) * 4;
        *(float4*)&As[r * 36 + c4] = tf32c4(areg[p]);
    }
#pragma unroll
    for (int p = 0; p < 4; p++) {
        int slot = tid + p * 256;
        int k = slot >> 3, b4 = (slot & 7) * 4;
        Bs[(b4 + 0) * 132 + k] = tf32c(breg[p].x);
        Bs[(b4 + 1) * 132 + k] = tf32c(breg[p].y);
        Bs[(b4 + 2) * 132 + k] = tf32c(breg[p].z);
        Bs[(b4 + 3) * 132 + k] = tf32c(breg[p].w);
    }
    __syncthreads();

    float acc[2][4][4] = {};
#pragma unroll 1
    for (int ch = 0; ch < 16; ch++) {
        if (ch < 15) {
            int bc = (ch + 1) * 32;
#pragma unroll
            for (int p = 0; p < 2; p++) {
                int slot = tid + p * 256;
                int r = slot >> 3, c4 = (slot & 7) * 4;
                areg[p] = make_float4(0.f, 0.f, 0.f, 0.f);
                if (v0 + r < VDIM)
                    areg[p] = *(const float4*)&g_ratio0[(size_t)(v0 + r) * BDIM + bc + c4];
            }
#pragma unroll
            for (int p = 0; p < 4; p++) {
                int slot = tid + p * 256;
                int k = slot >> 3, b4 = (slot & 7) * 4;
                breg[p] = *(const float4*)&theta0[(size_t)k * BDIM + bc + b4];
            }
        }
#pragma unroll
        for (int kk = 0; kk < 32; kk += 8) {
            float a[2][4], b[4][2];
#pragma unroll
            for (int ms = 0; ms < 2; ms++) {
                int base = (m0w + ms * 16 + grp) * 36 + kk + q;
                a[ms][0] = As[base];
                a[ms][1] = As[base + 8 * 36];
                a[ms][2] = As[base + 4];
                a[ms][3] = As[base + 8 * 36 + 4];
            }
#pragma unroll
            for (int ns = 0; ns < 4; ns++) {
                int cb = n0w + ns * 8 + grp;
                b[ns][0] = Bs[(kk + q) * 132 + cb];
                b[ns][1] = Bs[(kk + q + 4) * 132 + cb];
            }
#pragma unroll
            for (int ms = 0; ms < 2; ms++)
#pragma unroll
                for (int ns = 0; ns < 4; ns++)
                    mma_tf32(acc[ms][ns], a[ms][0], a[ms][1], a[ms][2], a[ms][3],
                             b[ns][0], b[ns][1]);
        }
        __syncthreads();
        if (ch < 15) {
#pragma unroll
            for (int p = 0; p < 2; p++) {
                int slot = tid + p * 256;
                int r = slot >> 3, c4 = (slot & 7) * 4;
                *(float4*)&As[r * 36 + c4] = tf32c4(areg[p]);
            }
#pragma unroll
            for (int p = 0; p < 4; p++) {
                int slot = tid + p * 256;
                int k = slot >> 3, b4 = (slot & 7) * 4;
                Bs[(b4 + 0) * 132 + k] = tf32c(breg[p].x);
                Bs[(b4 + 1) * 132 + k] = tf32c(breg[p].y);
                Bs[(b4 + 2) * 132 + k] = tf32c(breg[p].z);
                Bs[(b4 + 3) * 132 + k] = tf32c(breg[p].w);
            }
            __syncthreads();
        }
    }
#pragma unroll
    for (int ms = 0; ms < 2; ms++) {
        int m = v0 + m0w + ms * 16 + grp;
#pragma unroll
        for (int ns = 0; ns < 4; ns++) {
            int c = n0w + ns * 8 + 2 * q;
            if (m < VDIM) {
                float2 ph = *(const float2*)&phi0[(size_t)m * K0 + c];
                float2 o = {ph.x * acc[ms][ns][0], ph.y * acc[ms][ns][1]};
                *(float2*)&g_WSZS0[(size_t)m * K0 + c] = o;
            }
            if (m + 8 < VDIM) {
                float2 ph = *(const float2*)&phi0[(size_t)(m + 8) * K0 + c];
                float2 o = {ph.x * acc[ms][ns][2], ph.y * acc[ms][ns][3]};
                *(float2*)&g_WSZS0[(size_t)(m + 8) * K0 + c] = o;
            }
        }
    }
}

// ---------------------------------------------------------------------------
// 4) split-K partials of phi0^T @ ratio0 (deterministic)   tensor-core tf32
//    CTA 128(k) x 64(b); 8 warps (4m x 2n); contraction v chunk VCH=250
// ---------------------------------------------------------------------------
__global__ void __launch_bounds__(256)
k_x1part(const float* __restrict__ phi0) {
    __shared__ float As[128 * 36];   // [k][v-chunk] (phi0 transposed), pitch 36
    __shared__ float Bs[32 * 68];    // [v-chunk][b], pitch 68
    int tid = threadIdx.x;
    int b0 = blockIdx.x * 64;
    int s_ = blockIdx.y;
    int vbeg = s_ * VCH, vend = vbeg + VCH;
    int lane = tid & 31, wid = tid >> 5;
    int grp = lane >> 2, q = lane & 3;
    int m0w = (wid >> 1) * 32, n0w = (wid & 1) * 32;
    const int nsteps = (VCH + 31) / 32;   // 8 (tail zero-filled)
    float4 areg[4], breg[2];

    // prologue: chunk 0
#pragma unroll
    for (int p = 0; p < 4; p++) {
        int slot = tid + p * 256;
        int vv = slot & 31, k4 = (slot >> 5) * 4;
        int vg = vbeg + vv;
        areg[p] = make_float4(0.f, 0.f, 0.f, 0.f);
        if (vg < vend)
            areg[p] = *(const float4*)&phi0[(size_t)vg * K0 + k4];
    }
#pragma unroll
    for (int p = 0; p < 2; p++) {
        int slot = tid + p * 256;
        int vv = slot >> 4, j4 = (slot & 15) * 4;
        int vg = vbeg + vv;
        breg[p] = make_float4(0.f, 0.f, 0.f, 0.f);
        if (vg < vend)
            breg[p] = *(const float4*)&g_ratio0[(size_t)vg * BDIM + b0 + j4];
    }
#pragma unroll
    for (int p = 0; p < 4; p++) {
        int slot = tid + p * 256;
        int vv = slot & 31, k4 = (slot >> 5) * 4;
        As[(k4 + 0) * 36 + vv] = tf32c(areg[p].x);
        As[(k4 + 1) * 36 + vv] = tf32c(areg[p].y);
        As[(k4 + 2) * 36 + vv] = tf32c(areg[p].z);
        As[(k4 + 3) * 36 + vv] = tf32c(areg[p].w);
    }
#pragma unroll
    for (int p = 0; p < 2; p++) {
        int slot = tid + p * 256;
        int vv = slot >> 4, j4 = (slot & 15) * 4;
        *(float4*)&Bs[vv * 68 + j4] = tf32c4(breg[p]);
    }
    __syncthreads();

    float acc[2][2][4] = {};
    float acc2[2][2][4] = {};
#pragma unroll 1
    for (int ch = 0; ch < nsteps; ch++) {
        if (ch + 1 < nsteps) {
            int vb = vbeg + (ch + 1) * 32;
#pragma unroll
            for (int p = 0; p < 4; p++) {
                int slot = tid + p * 256;
                int vv = slot & 31, k4 = (slot >> 5) * 4;
                int vg = vb + vv;
                areg[p] = make_float4(0.f, 0.f, 0.f, 0.f);
                if (vg < vend)
                    areg[p] = *(const float4*)&phi0[(size_t)vg * K0 + k4];
            }
#pragma unroll
            for (int p = 0; p < 2; p++) {
                int slot = tid + p * 256;
                int vv = slot >> 4, j4 = (slot & 15) * 4;
                int vg = vb + vv;
                breg[p] = make_float4(0.f, 0.f, 0.f, 0.f);
                if (vg < vend)
                    breg[p] = *(const float4*)&g_ratio0[(size_t)vg * BDIM + b0 + j4];
            }
        }
#pragma unroll
        for (int kk = 0; kk < 32; kk += 8) {
            float a[2][4], b[4][2];
#pragma unroll
            for (int ms = 0; ms < 2; ms++) {
                int base = (m0w + ms * 16 + grp) * 36 + kk + q;
                a[ms][0] = As[base];
                a[ms][1] = As[base + 8 * 36];
                a[ms][2] = As[base + 4];
                a[ms][3] = As[base + 8 * 36 + 4];
            }
#pragma unroll
            for (int ns = 0; ns < 4; ns++) {
                int cb = n0w + ns * 8 + grp;
                b[ns][0] = Bs[(kk + q) * 68 + cb];
                b[ns][1] = Bs[(kk + q + 4) * 68 + cb];
            }
#pragma unroll
            for (int ms = 0; ms < 2; ms++) {
                mma_tf32(acc[ms][0],  a[ms][0], a[ms][1], a[ms][2], a[ms][3], b[0][0], b[0][1]);
                mma_tf32(acc[ms][1],  a[ms][0], a[ms][1], a[ms][2], a[ms][3], b[1][0], b[1][1]);
                mma_tf32(acc2[ms][0], a[ms][0], a[ms][1], a[ms][2], a[ms][3], b[2][0], b[2][1]);
                mma_tf32(acc2[ms][1], a[ms][0], a[ms][1], a[ms][2], a[ms][3], b[3][0], b[3][1]);
            }
        }
        __syncthreads();
        if (ch + 1 < nsteps) {
#pragma unroll
            for (int p = 0; p < 4; p++) {
                int slot = tid + p * 256;
                int vv = slot & 31, k4 = (slot >> 5) * 4;
                As[(k4 + 0) * 36 + vv] = tf32c(areg[p].x);
                As[(k4 + 1) * 36 + vv] = tf32c(areg[p].y);
                As[(k4 + 2) * 36 + vv] = tf32c(areg[p].z);
                As[(k4 + 3) * 36 + vv] = tf32c(areg[p].w);
            }
#pragma unroll
            for (int p = 0; p < 2; p++) {
                int slot = tid + p * 256;
                int vv = slot >> 4, j4 = (slot & 15) * 4;
                *(float4*)&Bs[vv * 68 + j4] = tf32c4(breg[p]);
            }
            __syncthreads();
        }
    }
    float* dst = &g_x1part[(size_t)s_ * K0 * BDIM];
#pragma unroll
    for (int ms = 0; ms < 2; ms++) {
        int kr = m0w + ms * 16 + grp;
#pragma unroll
        for (int ns = 0; ns < 4; ns++) {
            int c = b0 + n0w + ns * 8 + 2 * q;
            float* ac = (ns < 2) ? acc[ms][ns] : acc2[ms][ns - 2];
            *(float2*)&dst[(size_t)kr * BDIM + c]       = make_float2(ac[0], ac[1]);
            *(float2*)&dst[(size_t)(kr + 8) * BDIM + c] = make_float2(ac[2], ac[3]);
        }
    }
}

// 5) reduce partials, multiply by theta0 -> X1
__global__ void k_x1red(const float* __restrict__ theta0) {
    int idx = blockIdx.x * 1024 + threadIdx.x;
    float s = 0.f;
#pragma unroll 10
    for (int p = 0; p < NS0; p++) s += g_x1part[(size_t)p * K0 * BDIM + idx];
    g_X1[idx] = theta0[idx] * s;
}

// ---------------------------------------------------------------------------
// 6/7) column stats for layer-0 TLASGR
// ---------------------------------------------------------------------------
__global__ void k_colA(const float* __restrict__ phi0,
                       const float* __restrict__ noise0) {
    int t = threadIdx.x;
    int ch = blockIdx.x;
    float sw = 0.f, sp = 0.f, sn = 0.f;
    int vbeg = ch * RCH;
#pragma unroll 5
    for (int r = 0; r < RCH; r++) {
        size_t idx = (size_t)(vbeg + r) * K0 + t;
        sw += g_WSZS0[idx];
        float ph = phi0[idx];
        sp += ph;
        sn += sqrtf(ph) * noise0[idx];
    }
    g_c0part[ch * 384 + t]        = sw;
    g_c0part[ch * 384 + 128 + t]  = sp;
    g_c0part[ch * 384 + 256 + t]  = sn;
}

__global__ void k_colB() {
    int t = threadIdx.x;
    float sw = 0.f, sp = 0.f, sn = 0.f;
#pragma unroll 10
    for (int ch = 0; ch < NCH; ch++) {
        sw += g_c0part[ch * 384 + t];
        sp += g_c0part[ch * 384 + 128 + t];
        sn += g_c0part[ch * 384 + 256 + t];
    }
    float NDot   = 100.f * sw;
    float tmpsum = NDot + 0.1f * (float)VDIM;
    float inv_n  = 1.f / fmaxf(NDot, EPSV);
    float beta   = sqrtf(2.f * inv_n);
    float ssum   = sp + inv_n * (tmpsum - tmpsum * sp) + beta * sn;
    g_c0[t]           = inv_n;
    g_c0[128 + t]     = beta;
    g_c0[256 + t]     = tmpsum;
    g_c0[384 + t]     = ssum - 1.f;
}

// 8) p = max(EPS, step - (ssum-1)*phi); write + per-chunk psum
__global__ void k_p0(const float* __restrict__ phi0,
                     const float* __restrict__ noise0,
                     float* __restrict__ out) {
    int t = threadIdx.x;
    int ch = blockIdx.x;
    float inv_n = g_c0[t], beta = g_c0[128 + t];
    float tmpsum = g_c0[256 + t], c3 = g_c0[384 + t];
    float psum = 0.f;
    int vbeg = ch * RCH;
#pragma unroll 5
    for (int r = 0; r < RCH; r++) {
        size_t idx = (size_t)(vbeg + r) * K0 + t;
        float ph  = phi0[idx];
        float tmp = 100.f * g_WSZS0[idx] + 0.1f;
        float step = ph + inv_n * (tmp - tmpsum * ph)
                   + beta * sqrtf(ph) * noise0[idx];
        float p = fmaxf(EPSV, step - c3 * ph);
        out[idx] = p;
        psum += p;
    }
    g_ppart[ch * K0 + t] = psum;
}

__global__ void k_psumfin() {
    int t = threadIdx.x;
    float s = 0.f;
#pragma unroll 10
    for (int ch = 0; ch < NCH; ch++) s += g_ppart[ch * K0 + t];
    g_pinv0[t] = 1.f / fmaxf(EPSV, s);
}

__global__ void k_norm0(float* __restrict__ out) {
    int idx = blockIdx.x * 1024 + threadIdx.x;
    out[idx] *= g_pinv0[idx & 127];
}

// ---------------------------------------------------------------------------
// Layer 1: denom = phi1@theta1 (128x512, K=64), then elementwise digamma
// ---------------------------------------------------------------------------
__global__ void __launch_bounds__(256)
k_l1denom(const float* __restrict__ phi1, const float* __restrict__ theta1) {
    __shared__ float As[32][132];
    __shared__ float Bs[32][128];
    int tid = threadIdx.x;
    int b0 = blockIdx.x * 128;
    int tx = tid & 15, ty = tid >> 4;
    int row = ty * 8, col = tx * 8;
    float acc[8][8] = {};
    for (int k0 = 0; k0 < K1; k0 += 32) {
#pragma unroll
        for (int p = 0; p < 4; p++) {
            int slot = tid + p * 256;
            int r = slot >> 3, c4 = (slot & 7) * 4;
            float4 a = *(const float4*)&phi1[(size_t)r * K1 + k0 + c4];
            As[c4 + 0][r] = a.x; As[c4 + 1][r] = a.y;
            As[c4 + 2][r] = a.z; As[c4 + 3][r] = a.w;
        }
#pragma unroll
        for (int p = 0; p < 4; p++) {
            int slot = tid + p * 256;
            int c = slot >> 5, j4 = (slot & 31) * 4;
            *(float4*)&Bs[c][j4] =
                *(const float4*)&theta1[(size_t)(k0 + c) * BDIM + b0 + j4];
        }
        __syncthreads();
#pragma unroll
        for (int c = 0; c < 32; c++) {
            float4 a0 = *(const float4*)&As[c][row];
            float4 a1 = *(const float4*)&As[c][row + 4];
            float4 bv0 = *(const float4*)&Bs[c][col];
            float4 bv1 = *(const float4*)&Bs[c][col + 4];
            float ra[8] = {a0.x, a0.y, a0.z, a0.w, a1.x, a1.y, a1.z, a1.w};
            float rb[8] = {bv0.x, bv0.y, bv0.z, bv0.w, bv1.x, bv1.y, bv1.z, bv1.w};
#pragma unroll
            for (int i = 0; i < 8; i++)
#pragma unroll
                for (int j = 0; j < 8; j++) acc[i][j] += ra[i] * rb[j];
        }
        __syncthreads();
    }
#pragma unroll
    for (int i = 0; i < 8; i++)
#pragma unroll
        for (int j = 0; j < 8; j++)
            g_den1[(size_t)(row + i) * BDIM + b0 + col + j] = acc[i][j];
}

__global__ void k_l1dig() {
    int idx = blockIdx.x * 256 + threadIdx.x;   // 256 blocks -> 65536
    float d = fmaxf(g_den1[idx], EPSV);
    g_ratio1[idx] = digammaf_(d + g_X1[idx]) - digammaf_(d);
}

// Layer 1 WSZS partials: (128 x 64) = ratio1 @ theta1^T, split over b (8x64)
__global__ void k_l1wszs(const float* __restrict__ theta1) {
    __shared__ float As[32][132];
    __shared__ float Bs[32][68];
    int tid = threadIdx.x;
    int s = blockIdx.x;
    int bbase = s * 64;
    int tx = tid & 15, ty = tid >> 4;
    int row = ty * 8, col = tx * 4;
    float acc[8][4] = {};
    for (int bc = 0; bc < 64; bc += 32) {
        int b0 = bbase + bc;
#pragma unroll
        for (int p = 0; p < 4; p++) {
            int slot = tid + p * 256;
            int r = slot >> 3, c4 = (slot & 7) * 4;
            float4 a = *(const float4*)&g_ratio1[(size_t)r * BDIM + b0 + c4];
            As[c4 + 0][r] = a.x; As[c4 + 1][r] = a.y;
            As[c4 + 2][r] = a.z; As[c4 + 3][r] = a.w;
        }
#pragma unroll
        for (int p = 0; p < 2; p++) {
            int slot = tid + p * 256;
            int j = slot >> 3, c4 = (slot & 7) * 4;
            float4 t = *(const float4*)&theta1[(size_t)j * BDIM + b0 + c4];
            Bs[c4 + 0][j] = t.x; Bs[c4 + 1][j] = t.y;
            Bs[c4 + 2][j] = t.z; Bs[c4 + 3][j] = t.w;
        }
        __syncthreads();
#pragma unroll
        for (int c = 0; c < 32; c++) {
            float ra[8], rb[4];
#pragma unroll
            for (int i = 0; i < 8; i++) ra[i] = As[c][row + i];
#pragma unroll
            for (int j = 0; j < 4; j++) rb[j] = Bs[c][col + j];
#pragma unroll
            for (int i = 0; i < 8; i++)
#pragma unroll
                for (int j = 0; j < 4; j++) acc[i][j] += ra[i] * rb[j];
        }
        __syncthreads();
    }
    float* dst = &g_l1wp[(size_t)s * K0 * K1];
#pragma unroll
    for (int i = 0; i < 8; i++)
#pragma unroll
        for (int j = 0; j < 4; j++)
            dst[(size_t)(row + i) * K1 + col + j] = acc[i][j];
}

// Layer 1 counts: X2 = theta1 * (phi1^T @ ratio1), out (64, B), K=128
__global__ void k_l1x(const float* __restrict__ phi1,
                      const float* __restrict__ theta1) {
    __shared__ float As[32][64];
    __shared__ float Bs[32][128];
    int tid = threadIdx.x;
    int b0 = blockIdx.x * 128;
    int tx = tid & 15, ty = tid >> 4;
    int row = ty * 4, col = tx * 8;
    float acc[4][8] = {};
    for (int i0 = 0; i0 < K0; i0 += 32) {
#pragma unroll
        for (int p = 0; p < 2; p++) {
            int slot = tid + p * 256;
            int ii = slot >> 4, j4 = (slot & 15) * 4;
            *(float4*)&As[ii][j4] =
                *(const float4*)&phi1[(size_t)(i0 + ii) * K1 + j4];
        }
#pragma unroll
        for (int p = 0; p < 4; p++) {
            int slot = tid + p * 256;
            int ii = slot >> 5, j4 = (slot & 31) * 4;
            *(float4*)&Bs[ii][j4] =
                *(const float4*)&g_ratio1[(size_t)(i0 + ii) * BDIM + b0 + j4];
        }
        __syncthreads();
#pragma unroll
        for (int c = 0; c < 32; c++) {
            float ra[4], rb[8];
#pragma unroll
            for (int i = 0; i < 4; i++) ra[i] = As[c][row + i];
#pragma unroll
            for (int j = 0; j < 8; j++) rb[j] = Bs[c][col + j];
#pragma unroll
            for (int i = 0; i < 4; i++)
#pragma unroll
                for (int j = 0; j < 8; j++) acc[i][j] += ra[i] * rb[j];
        }
        __syncthreads();
    }
#pragma unroll
    for (int i = 0; i < 4; i++)
#pragma unroll
        for (int j = 0; j < 8; j++) {
            size_t idx = (size_t)(row + i) * BDIM + b0 + col + j;
            g_X2[idx] = theta1[idx] * acc[i][j];
        }
}

// Layer 1 TLASGR + simplex projection (one CTA, thread-per-column)
__global__ void k_l1tl(const float* __restrict__ phi1,
                       const float* __restrict__ noise1,
                       float* __restrict__ out) {
    __shared__ float sW[K0 * K1];
    int t = threadIdx.x;
    float sw = 0.f, sp = 0.f, sn = 0.f;
    for (int i = 0; i < K0; i++) {
        int idx = i * K1 + t;
        float w = 0.f;
#pragma unroll
        for (int s = 0; s < 8; s++) w += g_l1wp[s * K0 * K1 + idx];
        float ph = phi1[idx];
        w *= ph;
        sW[idx] = w;
        sw += w; sp += ph; sn += sqrtf(ph) * noise1[idx];
    }
    float NDot   = 100.f * sw;
    float tmpsum = NDot + 0.1f * (float)K0;
    float inv_n  = 1.f / fmaxf(NDot, EPSV);
    float beta   = sqrtf(2.f * inv_n);
    float ssum   = sp + inv_n * (tmpsum - tmpsum * sp) + beta * sn;
    float c3     = ssum - 1.f;
    float psum = 0.f;
    for (int i = 0; i < K0; i++) {
        int idx = i * K1 + t;
        float ph  = phi1[idx];
        float tmp = 100.f * sW[idx] + 0.1f;
        float step = ph + inv_n * (tmp - tmpsum * ph)
                   + beta * sqrtf(ph) * noise1[idx];
        float p = fmaxf(EPSV, step - c3 * ph);
        sW[idx] = p;
        psum += p;
    }
    float pinv = 1.f / fmaxf(EPSV, psum);
    for (int i = 0; i < K0; i++)
        out[OFF1 + i * K1 + t] = sW[i * K1 + t] * pinv;
}

// ---------------------------------------------------------------------------
// Layer 2: denom (64,B) K=32, then digamma
// ---------------------------------------------------------------------------
__global__ void k_l2denom(const float* __restrict__ phi2,
                          const float* __restrict__ theta2) {
    __shared__ float As[32][68];
    __shared__ float Bs[32][128];
    int tid = threadIdx.x;
    int b0 = blockIdx.x * 128;
    int tx = tid & 15, ty = tid >> 4;
    int row = ty * 4, col = tx * 8;
    float acc[4][8] = {};
    {
#pragma unroll
        for (int p = 0; p < 2; p++) {
            int slot = tid + p * 256;
            int r = slot >> 3, c4 = (slot & 7) * 4;
            float4 a = *(const float4*)&phi2[(size_t)r * K2 + c4];
            As[c4 + 0][r] = a.x; As[c4 + 1][r] = a.y;
            As[c4 + 2][r] = a.z; As[c4 + 3][r] = a.w;
        }
#pragma unroll
        for (int p = 0; p < 4; p++) {
            int slot = tid + p * 256;
            int c = slot >> 5, j4 = (slot & 31) * 4;
            *(float4*)&Bs[c][j4] =
                *(const float4*)&theta2[(size_t)c * BDIM + b0 + j4];
        }
        __syncthreads();
#pragma unroll
        for (int c = 0; c < 32; c++) {
            float ra[4], rb[8];
#pragma unroll
            for (int i = 0; i < 4; i++) ra[i] = As[c][row + i];
#pragma unroll
            for (int j = 0; j < 8; j++) rb[j] = Bs[c][col + j];
#pragma unroll
            for (int i = 0; i < 4; i++)
#pragma unroll
                for (int j = 0; j < 8; j++) acc[i][j] += ra[i] * rb[j];
        }
    }
#pragma unroll
    for (int i = 0; i < 4; i++)
#pragma unroll
        for (int j = 0; j < 8; j++)
            g_den2[(size_t)(row + i) * BDIM + b0 + col + j] = acc[i][j];
}

__global__ void k_l2dig() {
    int idx = blockIdx.x * 256 + threadIdx.x;   // 128 blocks -> 32768
    float d = fmaxf(g_den2[idx], EPSV);
    g_ratio2[idx] = digammaf_(d + g_X2[idx]) - digammaf_(d);
}

// Layer 2 WSZS partials: (64 x 32) = ratio2 @ theta2^T, split over b (8x64)
__global__ void k_l2wszs(const float* __restrict__ theta2) {
    __shared__ float As[32][68];
    __shared__ float Bs[32][36];
    int tid = threadIdx.x;
    int s = blockIdx.x;
    int bbase = s * 64;
    int tx = tid & 15, ty = tid >> 4;
    int row = ty * 4, col = tx * 2;
    float acc[4][2] = {};
    for (int bc = 0; bc < 64; bc += 32) {
        int b0 = bbase + bc;
#pragma unroll
        for (int p = 0; p < 2; p++) {
            int slot = tid + p * 256;
            int r = slot >> 3, c4 = (slot & 7) * 4;
            float4 a = *(const float4*)&g_ratio2[(size_t)r * BDIM + b0 + c4];
            As[c4 + 0][r] = a.x; As[c4 + 1][r] = a.y;
            As[c4 + 2][r] = a.z; As[c4 + 3][r] = a.w;
        }
        {
            int slot = tid;
            int j = slot >> 3, c4 = (slot & 7) * 4;
            float4 t = *(const float4*)&theta2[(size_t)j * BDIM + b0 + c4];
            Bs[c4 + 0][j] = t.x; Bs[c4 + 1][j] = t.y;
            Bs[c4 + 2][j] = t.z; Bs[c4 + 3][j] = t.w;
        }
        __syncthreads();
#pragma unroll
        for (int c = 0; c < 32; c++) {
            float ra[4], rb[2];
#pragma unroll
            for (int i = 0; i < 4; i++) ra[i] = As[c][row + i];
#pragma unroll
            for (int j = 0; j < 2; j++) rb[j] = Bs[c][col + j];
#pragma unroll
            for (int i = 0; i < 4; i++)
#pragma unroll
                for (int j = 0; j < 2; j++) acc[i][j] += ra[i] * rb[j];
        }
        __syncthreads();
    }
    float* dst = &g_l2wp[(size_t)s * K1 * K2];
#pragma unroll
    for (int i = 0; i < 4; i++)
#pragma unroll
        for (int j = 0; j < 2; j++)
            dst[(size_t)(row + i) * K2 + col + j] = acc[i][j];
}

// Layer 2 TLASGR (one CTA, 32 columns)
__global__ void k_l2tl(const float* __restrict__ phi2,
                       const float* __restrict__ noise2,
                       float* __restrict__ out) {
    __shared__ float sW[K1 * K2];
    int t = threadIdx.x;
    float sw = 0.f, sp = 0.f, sn = 0.f;
    for (int i = 0; i < K1; i++) {
        int idx = i * K2 + t;
        float w = 0.f;
#pragma unroll
        for (int s = 0; s < 8; s++) w += g_l2wp[s * K1 * K2 + idx];
        float ph = phi2[idx];
        w *= ph;
        sW[idx] = w;
        sw += w; sp += ph; sn += sqrtf(ph) * noise2[idx];
    }
    float NDot   = 100.f * sw;
    float tmpsum = NDot + 0.1f * (float)K1;
    float inv_n  = 1.f / fmaxf(NDot, EPSV);
    float beta   = sqrtf(2.f * inv_n);
    float ssum   = sp + inv_n * (tmpsum - tmpsum * sp) + beta * sn;
    float c3     = ssum - 1.f;
    float psum = 0.f;
    for (int i = 0; i < K1; i++) {
        int idx = i * K2 + t;
        float ph  = phi2[idx];
        float tmp = 100.f * sW[idx] + 0.1f;
        float step = ph + inv_n * (tmp - tmpsum * ph)
                   + beta * sqrtf(ph) * noise2[idx];
        float p = fmaxf(EPSV, step - c3 * ph);
        sW[idx] = p;
        psum += p;
    }
    float pinv = 1.f / fmaxf(EPSV, psum);
    for (int i = 0; i < K1; i++)
        out[OFF2 + i * K2 + t] = sW[i * K2 + t] * pinv;
}

// ---------------------------------------------------------------------------
// Launcher — static smem only; no attribute calls, no cp.async anywhere
// ---------------------------------------------------------------------------
extern "C" void kernel_launch(void* const* d_in, const int* in_sizes, int n_in,
                              void* d_out, int out_size) {
    const float* x      = (const float*)d_in[0];
    const float* theta0 = (const float*)d_in[1];
    const float* theta1 = (const float*)d_in[2];
    const float* theta2 = (const float*)d_in[3];
    const float* phi0   = (const float*)d_in[4];
    const float* phi1   = (const float*)d_in[5];
    const float* phi2   = (const float*)d_in[6];
    const float* noise0 = (const float*)d_in[7];
    const float* noise1 = (const float*)d_in[8];
    const float* noise2 = (const float*)d_in[9];
    float* out = (float*)d_out;

    // ---- layer 0 ----
    k_transpose<<<dim3((VDIM + 31) / 32, BDIM / 32), dim3(32, 8)>>>(x);
    k_ratio0<<<dim3((VDIM + 127) / 128, BDIM / 64), 256>>>(phi0, theta0);
    k_wszs0<<<dim3((VDIM + 63) / 64, 1), 256>>>(phi0, theta0);
    k_x1part<<<dim3(BDIM / 64, NS0), 256>>>(phi0);
    k_x1red<<<64, 1024>>>(theta0);
    k_colA<<<NCH, K0>>>(phi0, noise0);
    k_colB<<<1, K0>>>();
    k_p0<<<NCH, K0>>>(phi0, noise0, out);
    k_psumfin<<<1, K0>>>();
    k_norm0<<<3750, 1024>>>(out);

    // ---- layer 1 ----
    k_l1denom<<<BDIM / 128, 256>>>(phi1, theta1);
    k_l1dig<<<256, 256>>>();
    k_l1wszs<<<8, 256>>>(theta1);
    k_l1x<<<BDIM / 128, 256>>>(phi1, theta1);
    k_l1tl<<<1, K1>>>(phi1, noise1, out);

    // ---- layer 2 ----
    k_l2denom<<<BDIM / 128, 256>>>(phi2, theta2);
    k_l2dig<<<128, 256>>>();
    k_l2wszs<<<8, 256>>>(theta2);
    k_l2tl<<<1, K2>>>(phi2, noise2, out);
}